// round 3
// baseline (speedup 1.0000x reference)
#include <cuda_runtime.h>
#include <math_constants.h>

#define NR 131072
#define ZD 64
#define KC 2048
#define TK 64
#define TPB 256

// Scratch (no cudaMalloc allowed)
__device__ float  g_esq[KC];
__device__ double g_loss;

__global__ void k_init() { g_loss = 0.0; }

__global__ void k_esq(const float* __restrict__ e) {
    int k = blockIdx.x * blockDim.x + threadIdx.x;
    if (k < KC) {
        const float4* er = (const float4*)(e + (size_t)k * ZD);
        float s0 = 0.f, s1 = 0.f, s2 = 0.f, s3 = 0.f;
        #pragma unroll
        for (int i = 0; i < ZD / 4; i++) {
            float4 v = er[i];
            s0 = fmaf(v.x, v.x, s0);
            s1 = fmaf(v.y, v.y, s1);
            s2 = fmaf(v.z, v.z, s2);
            s3 = fmaf(v.w, v.w, s3);
        }
        g_esq[k] = (s0 + s1) + (s2 + s3);
    }
}

__global__ __launch_bounds__(TPB, 2)
void k_main(const float* __restrict__ z, const float* __restrict__ e,
            float* __restrict__ out) {
    __shared__ float4 es[TK][ZD / 4];
    __shared__ float  esq[TK];
    __shared__ float  red[TPB / 32];

    const int row = blockIdx.x * TPB + threadIdx.x;

    // Load this thread's z row into registers (64 floats).
    float zr[ZD];
    {
        const float4* zp = (const float4*)(z + (size_t)row * ZD);
        #pragma unroll
        for (int i = 0; i < ZD / 4; i++) {
            float4 v = zp[i];
            zr[4 * i + 0] = v.x; zr[4 * i + 1] = v.y;
            zr[4 * i + 2] = v.z; zr[4 * i + 3] = v.w;
        }
    }

    float best = CUDART_INF_F;
    int   bidx = 0;

    for (int kb = 0; kb < KC; kb += TK) {
        __syncthreads();
        // Stage TK codes (TK*ZD floats = 16 KB) into smem, coalesced float4.
        {
            const float4* ep = (const float4*)(e + (size_t)kb * ZD);
            #pragma unroll
            for (int i = 0; i < (TK * ZD / 4) / TPB; i++) {
                int idx = i * TPB + threadIdx.x;
                ((float4*)es)[idx] = ep[idx];
            }
            if (threadIdx.x < TK) esq[threadIdx.x] = g_esq[kb + threadIdx.x];
        }
        __syncthreads();

        #pragma unroll 2
        for (int k = 0; k < TK; k++) {
            float a0 = 0.f, a1 = 0.f, a2 = 0.f, a3 = 0.f;
            #pragma unroll
            for (int i = 0; i < ZD / 4; i++) {
                float4 ev = es[k][i];
                a0 = fmaf(zr[4 * i + 0], ev.x, a0);
                a1 = fmaf(zr[4 * i + 1], ev.y, a1);
                a2 = fmaf(zr[4 * i + 2], ev.z, a2);
                a3 = fmaf(zr[4 * i + 3], ev.w, a3);
            }
            float dot = (a0 + a1) + (a2 + a3);
            float d   = esq[k] - 2.0f * dot;     // z_sq omitted: constant per row
            if (d < best) { best = d; bidx = kb + k; }  // strict <: first index wins
        }
    }

    // Epilogue: gather winning code row (e is L2-resident), write z_q + index,
    // accumulate commit-loss contribution.
    float lsum = 0.f;
    {
        const float4* eb   = (const float4*)(e + (size_t)bidx * ZD);
        float4*       orow = (float4*)(out + (size_t)row * ZD);
        #pragma unroll
        for (int i = 0; i < ZD / 4; i++) {
            float4 v  = eb[i];
            float dx = zr[4 * i + 0] - v.x;
            float dy = zr[4 * i + 1] - v.y;
            float dz = zr[4 * i + 2] - v.z;
            float dw = zr[4 * i + 3] - v.w;
            lsum += dx * dx + dy * dy + dz * dz + dw * dw;
            orow[i] = v;
        }
    }
    out[(size_t)NR * ZD + row] = (float)bidx;

    // Loss reduction: warp shuffle, then one smem pass, one double atomic/block.
    #pragma unroll
    for (int s = 16; s > 0; s >>= 1)
        lsum += __shfl_xor_sync(0xFFFFFFFFu, lsum, s);
    if ((threadIdx.x & 31) == 0) red[threadIdx.x >> 5] = lsum;
    __syncthreads();
    if (threadIdx.x < TPB / 32) {
        float v = red[threadIdx.x];
        #pragma unroll
        for (int s = (TPB / 64); s > 0; s >>= 1)
            v += __shfl_xor_sync(0xFFFFFFFFu, v, s, TPB / 32);
        if (threadIdx.x == 0) atomicAdd(&g_loss, (double)v);
    }
}

__global__ void k_fin(float* __restrict__ out) {
    out[(size_t)NR * ZD + NR] = (float)(g_loss / ((double)NR * (double)ZD));
}

extern "C" void kernel_launch(void* const* d_in, const int* in_sizes, int n_in,
                              void* d_out, int out_size) {
    const float* z = (const float*)d_in[0];
    const float* e = (const float*)d_in[1];
    float* out = (float*)d_out;

    k_init<<<1, 1>>>();
    k_esq<<<(KC + 255) / 256, 256>>>(e);
    k_main<<<NR / TPB, TPB>>>(z, e, out);
    k_fin<<<1, 1>>>(out);
}

// round 8
// speedup vs baseline: 1.9583x; 1.9583x over previous
#include <cuda_runtime.h>
#include <math_constants.h>
#include <cstdint>

#define NR 131072
#define ZD 64
#define KC 2048
#define KE 192            // [zh|zh|zl] x [eh|el|eh]
#define MCTA 256
#define NTILE 128
#define NT (KC / NTILE)   // 16
#define TPB 256
#define GRID (NR / MCTA)  // 512
#define ROWB 400          // smem row stride (bytes); 400 % 128 == 16 -> ldmatrix conflict-free

// smem layout (bytes)
#define SM_A     0            // 256 x 400 = 102400
#define SM_B     102400       // 2 x 51200
#define BTILE_B  51200        // 128 x 400
#define SM_ESQ   204800       // 2048 f32
#define SMEM_TOTAL 212992
#define SM_CAND  102400       // overlays B after GEMM
#define CANDS    17           // padded stride (conflict-free)

__device__ __align__(16) unsigned short g_B[KC * KE];
__device__ float  g_esq[KC];
__device__ double g_loss;

__device__ __forceinline__ uint32_t smem_u32(const void* p) {
    uint32_t a;
    asm("{ .reg .u64 t; cvta.to.shared.u64 t, %1; cvt.u32.u64 %0, t; }" : "=r"(a) : "l"(p));
    return a;
}
__device__ __forceinline__ uint32_t f2bf(float x) {   // fp32 -> bf16 bits (RNE)
    uint32_t u = __float_as_uint(x);
    return (u + 0x7FFFu + ((u >> 16) & 1u)) >> 16;
}
__device__ __forceinline__ float bf2f(uint32_t b) { return __uint_as_float(b << 16); }

#define LDMX4(r0, r1, r2, r3, a)                                              \
    asm volatile("ldmatrix.sync.aligned.m8n8.x4.shared.b16 {%0,%1,%2,%3},[%4];" \
                 : "=r"(r0), "=r"(r1), "=r"(r2), "=r"(r3) : "r"(a))

#define MMA16816(c, a0, a1, a2, a3, b0, b1)                                   \
    asm volatile("mma.sync.aligned.m16n8k16.row.col.f32.bf16.bf16.f32 "       \
                 "{%0,%1,%2,%3},{%4,%5,%6,%7},{%8,%9},{%0,%1,%2,%3};"         \
                 : "+f"((c)[0]), "+f"((c)[1]), "+f"((c)[2]), "+f"((c)[3])     \
                 : "r"(a0), "r"(a1), "r"(a2), "r"(a3), "r"(b0), "r"(b1))

__global__ void k_init() { g_loss = 0.0; }

// Expanded codebook rows [eh | el | eh] + exact fp32 esq (R1 accumulation order).
__global__ void k_prep(const float* __restrict__ e) {
    int k = blockIdx.x * blockDim.x + threadIdx.x;
    if (k >= KC) return;
    const float* er = e + (size_t)k * ZD;
    unsigned short* br = g_B + (size_t)k * KE;
    float s0 = 0.f, s1 = 0.f, s2 = 0.f, s3 = 0.f;
    #pragma unroll
    for (int i = 0; i < ZD; i++) {
        float v = er[i];
        if ((i & 3) == 0) s0 = fmaf(v, v, s0);
        else if ((i & 3) == 1) s1 = fmaf(v, v, s1);
        else if ((i & 3) == 2) s2 = fmaf(v, v, s2);
        else s3 = fmaf(v, v, s3);
        uint32_t h = f2bf(v);
        uint32_t l = f2bf(v - bf2f(h));
        br[i]       = (unsigned short)h;
        br[64 + i]  = (unsigned short)l;
        br[128 + i] = (unsigned short)h;
    }
    g_esq[k] = (s0 + s1) + (s2 + s3);
}

__device__ __forceinline__ void prefetch_B(int t, int buf, uint32_t sb, int tid) {
    const char* src = (const char*)g_B + (size_t)t * NTILE * KE * 2;
    uint32_t dst0 = sb + SM_B + buf * BTILE_B;
    #pragma unroll
    for (int j = 0; j < 12; j++) {
        int ch = j * TPB + tid;          // 3072 chunks of 16B
        int row = ch / 24, c = ch % 24;
        asm volatile("cp.async.cg.shared.global [%0], [%1], 16;"
                     :: "r"(dst0 + row * ROWB + c * 16),
                        "l"(src + row * 384 + c * 16) : "memory");
    }
}

__global__ __launch_bounds__(TPB, 1)
void k_main(const float* __restrict__ z, const float* __restrict__ e,
            float* __restrict__ out) {
    extern __shared__ char smem[];
    const uint32_t sb = smem_u32(smem);
    const int tid = threadIdx.x, wid = tid >> 5, lane = tid & 31;
    const int mw = wid & 3, nw = wid >> 2;

    // ---- A: expand this CTA's 256 z-rows to [zh|zh|zl] (thread = row) ----
    {
        const float4* zp = (const float4*)(z + (size_t)(blockIdx.x * MCTA + tid) * ZD);
        char* ar = smem + SM_A + tid * ROWB;
        #pragma unroll
        for (int i = 0; i < 16; i++) {
            float4 v = zp[i];
            uint32_t h0 = f2bf(v.x), h1 = f2bf(v.y), h2 = f2bf(v.z), h3 = f2bf(v.w);
            uint32_t l0 = f2bf(v.x - bf2f(h0)), l1 = f2bf(v.y - bf2f(h1));
            uint32_t l2 = f2bf(v.z - bf2f(h2)), l3 = f2bf(v.w - bf2f(h3));
            uint32_t hp0 = h0 | (h1 << 16), hp1 = h2 | (h3 << 16);
            uint32_t lp0 = l0 | (l1 << 16), lp1 = l2 | (l3 << 16);
            *(uint32_t*)(ar + 8 * i)           = hp0;
            *(uint32_t*)(ar + 8 * i + 4)       = hp1;
            *(uint32_t*)(ar + 128 + 8 * i)     = hp0;
            *(uint32_t*)(ar + 128 + 8 * i + 4) = hp1;
            *(uint32_t*)(ar + 256 + 8 * i)     = lp0;
            *(uint32_t*)(ar + 256 + 8 * i + 4) = lp1;
        }
    }
    // esq -> smem
    {
        float4* d = (float4*)(smem + SM_ESQ);
        const float4* s = (const float4*)g_esq;
        #pragma unroll
        for (int i = 0; i < 2; i++) d[i * TPB + tid] = s[i * TPB + tid];
    }
    prefetch_B(0, 0, sb, tid);
    asm volatile("cp.async.commit_group;" ::: "memory");

    const float* esq_s = (const float*)(smem + SM_ESQ);

    // ldmatrix lane addresses
    // A x4 tiles: (m0,k0)(m8,k0)(m0,k8)(m8,k8)
    const uint32_t a_l = sb + SM_A
        + (uint32_t)(mw * 64 + (lane & 7) + ((lane >> 3) & 1) * 8) * ROWB
        + (lane >> 4) * 16;
    // B x4 tiles: (n0,k0)(n0,k8)(n8,k0)(n8,k8)
    const uint32_t b_l = sb + SM_B
        + (uint32_t)(nw * 64 + (lane & 7) + (lane >> 4) * 8) * ROWB
        + ((lane >> 3) & 1) * 16;

    float cb1[8], cb2[8];
    int   ci1[8], ci2[8];
    #pragma unroll
    for (int s = 0; s < 8; s++) { cb1[s] = CUDART_INF_F; cb2[s] = CUDART_INF_F; ci1[s] = 0; ci2[s] = 0; }

    for (int t = 0; t < NT; t++) {
        asm volatile("cp.async.wait_group 0;" ::: "memory");
        __syncthreads();
        if (t + 1 < NT) {
            prefetch_B(t + 1, (t + 1) & 1, sb, tid);
            asm volatile("cp.async.commit_group;" ::: "memory");
        }
        const uint32_t bb = b_l + (t & 1) * BTILE_B;

        float acc[4][8][4];
        #pragma unroll
        for (int f = 0; f < 4; f++)
            #pragma unroll
            for (int g = 0; g < 8; g++)
                #pragma unroll
                for (int q = 0; q < 4; q++) acc[f][g][q] = 0.f;

        #pragma unroll
        for (int ks = 0; ks < 12; ks++) {
            uint32_t bx[8], by[8];
            #pragma unroll
            for (int q = 0; q < 4; q++)
                LDMX4(bx[2 * q], by[2 * q], bx[2 * q + 1], by[2 * q + 1],
                      bb + q * 16 * ROWB + ks * 32);
            #pragma unroll
            for (int f = 0; f < 4; f++) {
                uint32_t a0, a1, a2, a3;
                LDMX4(a0, a1, a2, a3, a_l + f * 16 * ROWB + ks * 32);
                #pragma unroll
                for (int g = 0; g < 8; g++)
                    MMA16816(acc[f][g], a0, a1, a2, a3, bx[g], by[g]);
            }
        }

        // coarse distances + per-thread top-2 per row-slot
        const int colb = t * NTILE + nw * 64 + (lane & 3) * 2;
        #pragma unroll
        for (int f = 0; f < 4; f++) {
            #pragma unroll
            for (int g = 0; g < 8; g++) {
                const int col = colb + g * 8;
                const float e0 = esq_s[col], e1 = esq_s[col + 1];
                float d00 = fmaf(-2.f, acc[f][g][0], e0);
                float d01 = fmaf(-2.f, acc[f][g][1], e1);
                float d10 = fmaf(-2.f, acc[f][g][2], e0);
                float d11 = fmaf(-2.f, acc[f][g][3], e1);
                const int s0 = 2 * f, s1 = 2 * f + 1;
                if (d00 < cb1[s0]) { cb2[s0]=cb1[s0]; ci2[s0]=ci1[s0]; cb1[s0]=d00; ci1[s0]=col; }
                else if (d00 < cb2[s0]) { cb2[s0]=d00; ci2[s0]=col; }
                if (d01 < cb1[s0]) { cb2[s0]=cb1[s0]; ci2[s0]=ci1[s0]; cb1[s0]=d01; ci1[s0]=col+1; }
                else if (d01 < cb2[s0]) { cb2[s0]=d01; ci2[s0]=col+1; }
                if (d10 < cb1[s1]) { cb2[s1]=cb1[s1]; ci2[s1]=ci1[s1]; cb1[s1]=d10; ci1[s1]=col; }
                else if (d10 < cb2[s1]) { cb2[s1]=d10; ci2[s1]=col; }
                if (d11 < cb1[s1]) { cb2[s1]=cb1[s1]; ci2[s1]=ci1[s1]; cb1[s1]=d11; ci1[s1]=col+1; }
                else if (d11 < cb2[s1]) { cb2[s1]=d11; ci2[s1]=col+1; }
            }
        }
    }

    // ---- publish candidates (overlay B region) ----
    __syncthreads();
    float* candd = (float*)(smem + SM_CAND);
    int*   candi = (int*)(smem + SM_CAND + MCTA * CANDS * 4);
    #pragma unroll
    for (int s = 0; s < 8; s++) {
        int rl = mw * 64 + (s >> 1) * 16 + (lane >> 2) + (s & 1) * 8;
        int p  = (nw * 4 + (lane & 3)) * 2;
        candd[rl * CANDS + p]     = cb1[s];  candi[rl * CANDS + p]     = ci1[s];
        candd[rl * CANDS + p + 1] = cb2[s];  candi[rl * CANDS + p + 1] = ci2[s];
    }
    __syncthreads();

    // ---- rescue: pick 4 coarsely-best of 16, rescore exact fp32 (R1 numerics) ----
    const int row = blockIdx.x * MCTA + tid;
    float zr[ZD];
    {
        const float4* zp = (const float4*)(z + (size_t)row * ZD);
        #pragma unroll
        for (int i = 0; i < ZD / 4; i++) {
            float4 v = zp[i];
            zr[4*i] = v.x; zr[4*i+1] = v.y; zr[4*i+2] = v.z; zr[4*i+3] = v.w;
        }
    }
    uint32_t usedm = 0;
    float bd = CUDART_INF_F;
    int   bi = KC;
    #pragma unroll
    for (int j = 0; j < 4; j++) {
        float mn = CUDART_INF_F; int mp = 0;
        for (int p = 0; p < 16; p++) {
            if ((usedm >> p) & 1u) continue;
            float d = candd[tid * CANDS + p];
            if (d < mn) { mn = d; mp = p; }
        }
        usedm |= 1u << mp;
        int idx = candi[tid * CANDS + mp];
        const float4* ep = (const float4*)(e + (size_t)idx * ZD);
        float a0=0.f,a1=0.f,a2=0.f,a3=0.f;
        #pragma unroll
        for (int i = 0; i < ZD / 4; i++) {
            float4 v = ep[i];
            a0 = fmaf(zr[4*i],   v.x, a0); a1 = fmaf(zr[4*i+1], v.y, a1);
            a2 = fmaf(zr[4*i+2], v.z, a2); a3 = fmaf(zr[4*i+3], v.w, a3);
        }
        float d = esq_s[idx] - 2.0f * ((a0 + a1) + (a2 + a3));
        if (d < bd || (d == bd && idx < bi)) { bd = d; bi = idx; }
    }

    // ---- outputs: z_q row, index, loss ----
    float lsum = 0.f;
    {
        const float4* ep = (const float4*)(e + (size_t)bi * ZD);
        float4* orow = (float4*)(out + (size_t)row * ZD);
        #pragma unroll
        for (int i = 0; i < ZD / 4; i++) {
            float4 v = ep[i];
            float dx = zr[4*i]   - v.x, dy = zr[4*i+1] - v.y;
            float dz = zr[4*i+2] - v.z, dw = zr[4*i+3] - v.w;
            lsum += dx*dx + dy*dy + dz*dz + dw*dw;
            orow[i] = v;
        }
    }
    out[(size_t)NR * ZD + row] = (float)bi;

    #pragma unroll
    for (int s = 16; s > 0; s >>= 1)
        lsum += __shfl_xor_sync(0xFFFFFFFFu, lsum, s);
    if (lane == 0) atomicAdd(&g_loss, (double)lsum);
}

__global__ void k_fin(float* __restrict__ out) {
    out[(size_t)NR * ZD + NR] = (float)(g_loss / ((double)NR * (double)ZD));
}

extern "C" void kernel_launch(void* const* d_in, const int* in_sizes, int n_in,
                              void* d_out, int out_size) {
    const float* z = (const float*)d_in[0];
    const float* e = (const float*)d_in[1];
    float* out = (float*)d_out;

    cudaFuncSetAttribute(k_main, cudaFuncAttributeMaxDynamicSharedMemorySize, SMEM_TOTAL);
    k_init<<<1, 1>>>();
    k_prep<<<(KC + 127) / 128, 128>>>(e);
    k_main<<<GRID, TPB, SMEM_TOTAL>>>(z, e, out);
    k_fin<<<1, 1>>>(out);
}

// round 9
// speedup vs baseline: 2.7152x; 1.3865x over previous
#include <cuda_runtime.h>
#include <cuda_fp16.h>
#include <math_constants.h>
#include <cstdint>

#define NR 131072
#define ZD 64
#define KC 2048
#define MCTA 256
#define NTILE 128
#define NT (KC / NTILE)   // 16
#define TPB 256
#define GRID (NR / MCTA)  // 512
#define ROWB 144          // smem row stride (128B data + 16 pad) -> ldmatrix conflict-free

// smem layout (bytes)
#define SM_A     0            // 256 x 144 = 36864
#define SM_B     36864        // 2 x 18432
#define BTILE_B  18432        // 128 x 144
#define SM_ESQ   73728        // 2048 f32
#define SMEM_TOTAL 81920
#define SM_CAND  36864        // overlays B after GEMM (needs 34816 B)
#define CANDS    17           // padded stride

__device__ __align__(16) unsigned short g_B[KC * ZD];   // fp16 codebook, K-major
__device__ float  g_esq[KC];
__device__ double g_loss;

__device__ __forceinline__ uint32_t smem_u32(const void* p) {
    uint32_t a;
    asm("{ .reg .u64 t; cvta.to.shared.u64 t, %1; cvt.u32.u64 %0, t; }" : "=r"(a) : "l"(p));
    return a;
}

#define LDMX4(r0, r1, r2, r3, a)                                              \
    asm volatile("ldmatrix.sync.aligned.m8n8.x4.shared.b16 {%0,%1,%2,%3},[%4];" \
                 : "=r"(r0), "=r"(r1), "=r"(r2), "=r"(r3) : "r"(a))

#define MMA16816(c, a0, a1, a2, a3, b0, b1)                                   \
    asm volatile("mma.sync.aligned.m16n8k16.row.col.f32.f16.f16.f32 "         \
                 "{%0,%1,%2,%3},{%4,%5,%6,%7},{%8,%9},{%0,%1,%2,%3};"         \
                 : "+f"((c)[0]), "+f"((c)[1]), "+f"((c)[2]), "+f"((c)[3])     \
                 : "r"(a0), "r"(a1), "r"(a2), "r"(a3), "r"(b0), "r"(b1))

__global__ void k_init() { g_loss = 0.0; }

// fp16 codebook + exact fp32 esq (R1 accumulation order).
__global__ void k_prep(const float* __restrict__ e) {
    int k = blockIdx.x * blockDim.x + threadIdx.x;
    if (k >= KC) return;
    const float* er = e + (size_t)k * ZD;
    unsigned short* br = g_B + (size_t)k * ZD;
    float s0 = 0.f, s1 = 0.f, s2 = 0.f, s3 = 0.f;
    #pragma unroll
    for (int i = 0; i < ZD; i++) {
        float v = er[i];
        if ((i & 3) == 0) s0 = fmaf(v, v, s0);
        else if ((i & 3) == 1) s1 = fmaf(v, v, s1);
        else if ((i & 3) == 2) s2 = fmaf(v, v, s2);
        else s3 = fmaf(v, v, s3);
        br[i] = __half_as_ushort(__float2half_rn(v));
    }
    g_esq[k] = (s0 + s1) + (s2 + s3);
}

__device__ __forceinline__ void prefetch_B(int t, int buf, uint32_t sb, int tid) {
    const char* src = (const char*)g_B + (size_t)t * NTILE * ZD * 2;
    uint32_t dst0 = sb + SM_B + buf * BTILE_B;
    #pragma unroll
    for (int j = 0; j < 4; j++) {
        int ch = j * TPB + tid;          // 1024 chunks of 16B
        int row = ch >> 3, c = ch & 7;
        asm volatile("cp.async.cg.shared.global [%0], [%1], 16;"
                     :: "r"(dst0 + row * ROWB + c * 16),
                        "l"(src + row * 128 + c * 16) : "memory");
    }
}

__global__ __launch_bounds__(TPB, 1)
void k_main(const float* __restrict__ z, const float* __restrict__ e,
            float* __restrict__ out) {
    extern __shared__ char smem[];
    const uint32_t sb = smem_u32(smem);
    const int tid = threadIdx.x, wid = tid >> 5, lane = tid & 31;
    const int mw = wid & 3, nw = wid >> 2;

    // ---- A: convert this CTA's 256 z-rows to fp16 (thread = row) ----
    {
        const float4* zp = (const float4*)(z + (size_t)(blockIdx.x * MCTA + tid) * ZD);
        char* ar = smem + SM_A + tid * ROWB;
        #pragma unroll
        for (int i = 0; i < 16; i++) {
            float4 v = zp[i];
            __half2 p0 = __floats2half2_rn(v.x, v.y);
            __half2 p1 = __floats2half2_rn(v.z, v.w);
            *(uint32_t*)(ar + 8 * i)     = *reinterpret_cast<uint32_t*>(&p0);
            *(uint32_t*)(ar + 8 * i + 4) = *reinterpret_cast<uint32_t*>(&p1);
        }
    }
    // esq -> smem
    {
        float4* d = (float4*)(smem + SM_ESQ);
        const float4* s = (const float4*)g_esq;
        #pragma unroll
        for (int i = 0; i < 2; i++) d[i * TPB + tid] = s[i * TPB + tid];
    }
    prefetch_B(0, 0, sb, tid);
    asm volatile("cp.async.commit_group;" ::: "memory");

    const float* esq_s = (const float*)(smem + SM_ESQ);

    // ldmatrix lane addresses (mappings verified in R8)
    const uint32_t a_l = sb + SM_A
        + (uint32_t)(mw * 64 + (lane & 7) + ((lane >> 3) & 1) * 8) * ROWB
        + (lane >> 4) * 16;
    const uint32_t b_l = sb + SM_B
        + (uint32_t)(nw * 64 + (lane & 7) + (lane >> 4) * 8) * ROWB
        + ((lane >> 3) & 1) * 16;

    float cb1[8], cb2[8];
    int   ci1[8], ci2[8];
    #pragma unroll
    for (int s = 0; s < 8; s++) { cb1[s] = CUDART_INF_F; cb2[s] = CUDART_INF_F; ci1[s] = 0; ci2[s] = 0; }

    for (int t = 0; t < NT; t++) {
        asm volatile("cp.async.wait_group 0;" ::: "memory");
        __syncthreads();
        if (t + 1 < NT) {
            prefetch_B(t + 1, (t + 1) & 1, sb, tid);
            asm volatile("cp.async.commit_group;" ::: "memory");
        }
        const uint32_t bb = b_l + (t & 1) * BTILE_B;

        float acc[4][8][4];
        #pragma unroll
        for (int f = 0; f < 4; f++)
            #pragma unroll
            for (int g = 0; g < 8; g++)
                #pragma unroll
                for (int q = 0; q < 4; q++) acc[f][g][q] = 0.f;

        #pragma unroll
        for (int ks = 0; ks < 4; ks++) {
            uint32_t bx[8], by[8];
            #pragma unroll
            for (int q = 0; q < 4; q++)
                LDMX4(bx[2 * q], by[2 * q], bx[2 * q + 1], by[2 * q + 1],
                      bb + q * 16 * ROWB + ks * 32);
            #pragma unroll
            for (int f = 0; f < 4; f++) {
                uint32_t a0, a1, a2, a3;
                LDMX4(a0, a1, a2, a3, a_l + f * 16 * ROWB + ks * 32);
                #pragma unroll
                for (int g = 0; g < 8; g++)
                    MMA16816(acc[f][g], a0, a1, a2, a3, bx[g], by[g]);
            }
        }

        // coarse distances + per-thread top-2 per row-slot
        const int colb = t * NTILE + nw * 64 + (lane & 3) * 2;
        #pragma unroll
        for (int f = 0; f < 4; f++) {
            #pragma unroll
            for (int g = 0; g < 8; g++) {
                const int col = colb + g * 8;
                const float e0 = esq_s[col], e1 = esq_s[col + 1];
                float d00 = fmaf(-2.f, acc[f][g][0], e0);
                float d01 = fmaf(-2.f, acc[f][g][1], e1);
                float d10 = fmaf(-2.f, acc[f][g][2], e0);
                float d11 = fmaf(-2.f, acc[f][g][3], e1);
                const int s0 = 2 * f, s1 = 2 * f + 1;
                if (d00 < cb1[s0]) { cb2[s0]=cb1[s0]; ci2[s0]=ci1[s0]; cb1[s0]=d00; ci1[s0]=col; }
                else if (d00 < cb2[s0]) { cb2[s0]=d00; ci2[s0]=col; }
                if (d01 < cb1[s0]) { cb2[s0]=cb1[s0]; ci2[s0]=ci1[s0]; cb1[s0]=d01; ci1[s0]=col+1; }
                else if (d01 < cb2[s0]) { cb2[s0]=d01; ci2[s0]=col+1; }
                if (d10 < cb1[s1]) { cb2[s1]=cb1[s1]; ci2[s1]=ci1[s1]; cb1[s1]=d10; ci1[s1]=col; }
                else if (d10 < cb2[s1]) { cb2[s1]=d10; ci2[s1]=col; }
                if (d11 < cb1[s1]) { cb2[s1]=cb1[s1]; ci2[s1]=ci1[s1]; cb1[s1]=d11; ci1[s1]=col+1; }
                else if (d11 < cb2[s1]) { cb2[s1]=d11; ci2[s1]=col+1; }
            }
        }
    }

    // ---- publish candidates (overlay B region) ----
    __syncthreads();
    float* candd = (float*)(smem + SM_CAND);
    int*   candi = (int*)(smem + SM_CAND + MCTA * CANDS * 4);
    #pragma unroll
    for (int s = 0; s < 8; s++) {
        int rl = mw * 64 + (s >> 1) * 16 + (lane >> 2) + (s & 1) * 8;
        int p  = (nw * 4 + (lane & 3)) * 2;
        candd[rl * CANDS + p]     = cb1[s];  candi[rl * CANDS + p]     = ci1[s];
        candd[rl * CANDS + p + 1] = cb2[s];  candi[rl * CANDS + p + 1] = ci2[s];
    }
    __syncthreads();

    // ---- rescue: pick 4 coarsely-best of 16, rescore exact fp32 (R1 numerics) ----
    const int row = blockIdx.x * MCTA + tid;
    float zr[ZD];
    {
        const float4* zp = (const float4*)(z + (size_t)row * ZD);
        #pragma unroll
        for (int i = 0; i < ZD / 4; i++) {
            float4 v = zp[i];
            zr[4*i] = v.x; zr[4*i+1] = v.y; zr[4*i+2] = v.z; zr[4*i+3] = v.w;
        }
    }
    uint32_t usedm = 0;
    float bd = CUDART_INF_F;
    int   bi = KC;
    #pragma unroll
    for (int j = 0; j < 4; j++) {
        float mn = CUDART_INF_F; int mp = 0;
        for (int p = 0; p < 16; p++) {
            if ((usedm >> p) & 1u) continue;
            float d = candd[tid * CANDS + p];
            if (d < mn) { mn = d; mp = p; }
        }
        usedm |= 1u << mp;
        int idx = candi[tid * CANDS + mp];
        const float4* ep = (const float4*)(e + (size_t)idx * ZD);
        float a0=0.f,a1=0.f,a2=0.f,a3=0.f;
        #pragma unroll
        for (int i = 0; i < ZD / 4; i++) {
            float4 v = ep[i];
            a0 = fmaf(zr[4*i],   v.x, a0); a1 = fmaf(zr[4*i+1], v.y, a1);
            a2 = fmaf(zr[4*i+2], v.z, a2); a3 = fmaf(zr[4*i+3], v.w, a3);
        }
        float d = esq_s[idx] - 2.0f * ((a0 + a1) + (a2 + a3));
        if (d < bd || (d == bd && idx < bi)) { bd = d; bi = idx; }
    }

    // ---- outputs: z_q row, index, loss ----
    float lsum = 0.f;
    {
        const float4* ep = (const float4*)(e + (size_t)bi * ZD);
        float4* orow = (float4*)(out + (size_t)row * ZD);
        #pragma unroll
        for (int i = 0; i < ZD / 4; i++) {
            float4 v = ep[i];
            float dx = zr[4*i]   - v.x, dy = zr[4*i+1] - v.y;
            float dz = zr[4*i+2] - v.z, dw = zr[4*i+3] - v.w;
            lsum += dx*dx + dy*dy + dz*dz + dw*dw;
            orow[i] = v;
        }
    }
    out[(size_t)NR * ZD + row] = (float)bi;

    #pragma unroll
    for (int s = 16; s > 0; s >>= 1)
        lsum += __shfl_xor_sync(0xFFFFFFFFu, lsum, s);
    if (lane == 0) atomicAdd(&g_loss, (double)lsum);
}

__global__ void k_fin(float* __restrict__ out) {
    out[(size_t)NR * ZD + NR] = (float)(g_loss / ((double)NR * (double)ZD));
}

extern "C" void kernel_launch(void* const* d_in, const int* in_sizes, int n_in,
                              void* d_out, int out_size) {
    const float* z = (const float*)d_in[0];
    const float* e = (const float*)d_in[1];
    float* out = (float*)d_out;

    cudaFuncSetAttribute(k_main, cudaFuncAttributeMaxDynamicSharedMemorySize, SMEM_TOTAL);
    k_init<<<1, 1>>>();
    k_prep<<<(KC + 127) / 128, 128>>>(e);
    k_main<<<GRID, TPB, SMEM_TOTAL>>>(z, e, out);
    k_fin<<<1, 1>>>(out);
}

// round 10
// speedup vs baseline: 5.0457x; 1.8583x over previous
#include <cuda_runtime.h>
#include <cuda_fp16.h>
#include <math_constants.h>
#include <cstdint>

#define NR 131072
#define ZD 64
#define KC 2048
#define MCTA 256
#define NTILE 128
#define NT (KC / NTILE)   // 16
#define TPB 256
#define GRID (NR / MCTA)  // 512
#define ROWB 144          // smem row stride (128B data + 16 pad) -> ldmatrix conflict-free

// smem layout (bytes)
#define SM_A     0            // 256 x 144 = 36864
#define SM_B     36864        // 2 x 18432
#define BTILE_B  18432        // 128 x 144
#define SM_ESQ   73728        // 2048 f32 (exact, for rescore)
#define SM_ZSQ   81920        // 256 f32 (per-row bias)
#define SMEM_TOTAL 82944
#define SM_CAND  36864        // overlays B after GEMM (needs 17408 B)
#define CANDS    17           // padded stride

__device__ __align__(16) unsigned short g_B[KC * ZD];   // fp16 codebook, K-major
__device__ float  g_esq[KC];
__device__ double g_loss;

__device__ __forceinline__ uint32_t smem_u32(const void* p) {
    uint32_t a;
    asm("{ .reg .u64 t; cvta.to.shared.u64 t, %1; cvt.u32.u64 %0, t; }" : "=r"(a) : "l"(p));
    return a;
}

#define LDMX4(r0, r1, r2, r3, a)                                              \
    asm volatile("ldmatrix.sync.aligned.m8n8.x4.shared.b16 {%0,%1,%2,%3},[%4];" \
                 : "=r"(r0), "=r"(r1), "=r"(r2), "=r"(r3) : "r"(a))

#define MMA16816(c, a0, a1, a2, a3, b0, b1)                                   \
    asm volatile("mma.sync.aligned.m16n8k16.row.col.f32.f16.f16.f32 "         \
                 "{%0,%1,%2,%3},{%4,%5,%6,%7},{%8,%9},{%0,%1,%2,%3};"         \
                 : "+f"((c)[0]), "+f"((c)[1]), "+f"((c)[2]), "+f"((c)[3])     \
                 : "r"(a0), "r"(a1), "r"(a2), "r"(a3), "r"(b0), "r"(b1))

// branchless top-2 on packed (distance|index) keys: 3 IMNMX
#define TOP2(b1, b2, k) do {                       \
    uint32_t _mx = max((b1), (k));                 \
    (b1) = min((b1), (k));                         \
    (b2) = min((b2), _mx); } while (0)

// key = (bits(d') & ~0x7FF) | idx  -> single LOP3 (d' guaranteed positive)
__device__ __forceinline__ uint32_t packkey(float d, int idx) {
    return (__float_as_uint(d) & 0xFFFFF800u) | (uint32_t)idx;
}

__global__ void k_init() { g_loss = 0.0; }

// fp16 codebook + exact fp32 esq (R1 accumulation order).
__global__ void k_prep(const float* __restrict__ e) {
    int k = blockIdx.x * blockDim.x + threadIdx.x;
    if (k >= KC) return;
    const float* er = e + (size_t)k * ZD;
    unsigned short* br = g_B + (size_t)k * ZD;
    float s0 = 0.f, s1 = 0.f, s2 = 0.f, s3 = 0.f;
    #pragma unroll
    for (int i = 0; i < ZD; i++) {
        float v = er[i];
        if ((i & 3) == 0) s0 = fmaf(v, v, s0);
        else if ((i & 3) == 1) s1 = fmaf(v, v, s1);
        else if ((i & 3) == 2) s2 = fmaf(v, v, s2);
        else s3 = fmaf(v, v, s3);
        br[i] = __half_as_ushort(__float2half_rn(v));
    }
    g_esq[k] = (s0 + s1) + (s2 + s3);
}

__device__ __forceinline__ void prefetch_B(int t, int buf, uint32_t sb, int tid) {
    const char* src = (const char*)g_B + (size_t)t * NTILE * ZD * 2;
    uint32_t dst0 = sb + SM_B + buf * BTILE_B;
    #pragma unroll
    for (int j = 0; j < 4; j++) {
        int ch = j * TPB + tid;          // 1024 chunks of 16B
        int row = ch >> 3, c = ch & 7;
        asm volatile("cp.async.cg.shared.global [%0], [%1], 16;"
                     :: "r"(dst0 + row * ROWB + c * 16),
                        "l"(src + row * 128 + c * 16) : "memory");
    }
}

__global__ __launch_bounds__(TPB, 1)
void k_main(const float* __restrict__ z, const float* __restrict__ e,
            float* __restrict__ out) {
    extern __shared__ char smem[];
    const uint32_t sb = smem_u32(smem);
    const int tid = threadIdx.x, wid = tid >> 5, lane = tid & 31;
    const int mw = wid & 3, nw = wid >> 2;

    // ---- A: convert this CTA's 256 z-rows to fp16; record z^2 bias ----
    {
        const float4* zp = (const float4*)(z + (size_t)(blockIdx.x * MCTA + tid) * ZD);
        char* ar = smem + SM_A + tid * ROWB;
        float zs = 0.f;
        #pragma unroll
        for (int i = 0; i < 16; i++) {
            float4 v = zp[i];
            zs += v.x * v.x + v.y * v.y + v.z * v.z + v.w * v.w;
            __half2 p0 = __floats2half2_rn(v.x, v.y);
            __half2 p1 = __floats2half2_rn(v.z, v.w);
            *(uint32_t*)(ar + 8 * i)     = *reinterpret_cast<uint32_t*>(&p0);
            *(uint32_t*)(ar + 8 * i + 4) = *reinterpret_cast<uint32_t*>(&p1);
        }
        ((float*)(smem + SM_ZSQ))[tid] = zs;
    }
    // esq -> smem (exact values, used for bias-free rescore too)
    {
        float4* d = (float4*)(smem + SM_ESQ);
        const float4* s = (const float4*)g_esq;
        #pragma unroll
        for (int i = 0; i < 2; i++) d[i * TPB + tid] = s[i * TPB + tid];
    }
    prefetch_B(0, 0, sb, tid);
    asm volatile("cp.async.commit_group;" ::: "memory");

    const float* esq_s = (const float*)(smem + SM_ESQ);

    // ldmatrix lane addresses (mappings verified R8/R9)
    const uint32_t a_l = sb + SM_A
        + (uint32_t)(mw * 64 + (lane & 7) + ((lane >> 3) & 1) * 8) * ROWB
        + (lane >> 4) * 16;
    const uint32_t b_l = sb + SM_B
        + (uint32_t)(nw * 64 + (lane & 7) + (lane >> 4) * 8) * ROWB
        + ((lane >> 3) & 1) * 16;

    uint32_t kb1[8], kb2[8];
    #pragma unroll
    for (int s = 0; s < 8; s++) { kb1[s] = 0xFFFFFFFFu; kb2[s] = 0xFFFFFFFFu; }

    // per-slot row bias z^2 (needs the conversion sync below first)
    float zsq[8];

    for (int t = 0; t < NT; t++) {
        asm volatile("cp.async.wait_group 0;" ::: "memory");
        __syncthreads();
        if (t == 0) {
            const float* zq = (const float*)(smem + SM_ZSQ);
            #pragma unroll
            for (int s = 0; s < 8; s++)
                zsq[s] = zq[mw * 64 + (s >> 1) * 16 + (lane >> 2) + (s & 1) * 8];
        }
        if (t + 1 < NT) {
            prefetch_B(t + 1, (t + 1) & 1, sb, tid);
            asm volatile("cp.async.commit_group;" ::: "memory");
        }
        const uint32_t bb = b_l + (t & 1) * BTILE_B;
        const int colb0 = t * NTILE + nw * 64 + (lane & 3) * 2;

        #pragma unroll
        for (int h = 0; h < 2; h++) {        // N-half: g = h*4 + gg
            float acc[4][4][4];
            #pragma unroll
            for (int f = 0; f < 4; f++)
                #pragma unroll
                for (int g = 0; g < 4; g++)
                    #pragma unroll
                    for (int q = 0; q < 4; q++) acc[f][g][q] = 0.f;

            #pragma unroll
            for (int ks = 0; ks < 4; ks++) {
                uint32_t bx[4], by[4];
                LDMX4(bx[0], by[0], bx[1], by[1], bb + (2 * h + 0) * 16 * ROWB + ks * 32);
                LDMX4(bx[2], by[2], bx[3], by[3], bb + (2 * h + 1) * 16 * ROWB + ks * 32);
                #pragma unroll
                for (int f = 0; f < 4; f++) {
                    uint32_t a0, a1, a2, a3;
                    LDMX4(a0, a1, a2, a3, a_l + f * 16 * ROWB + ks * 32);
                    #pragma unroll
                    for (int g = 0; g < 4; g++)
                        MMA16816(acc[f][g], a0, a1, a2, a3, bx[g], by[g]);
                }
            }

            const int colb = colb0 + h * 32;
            #pragma unroll
            for (int g = 0; g < 4; g++) {
                const int col = colb + g * 8;
                const float e0 = esq_s[col], e1 = esq_s[col + 1];
                #pragma unroll
                for (int f = 0; f < 4; f++) {
                    const int s0 = 2 * f, s1 = 2 * f + 1;
                    float d00 = fmaf(-2.f, acc[f][g][0], e0) + zsq[s0];
                    float d01 = fmaf(-2.f, acc[f][g][1], e1) + zsq[s0];
                    float d10 = fmaf(-2.f, acc[f][g][2], e0) + zsq[s1];
                    float d11 = fmaf(-2.f, acc[f][g][3], e1) + zsq[s1];
                    uint32_t k00 = packkey(d00, col);
                    uint32_t k01 = packkey(d01, col + 1);
                    uint32_t k10 = packkey(d10, col);
                    uint32_t k11 = packkey(d11, col + 1);
                    TOP2(kb1[s0], kb2[s0], k00);
                    TOP2(kb1[s0], kb2[s0], k01);
                    TOP2(kb1[s1], kb2[s1], k10);
                    TOP2(kb1[s1], kb2[s1], k11);
                }
            }
        }
    }

    // ---- publish candidate keys (overlay B region) ----
    __syncthreads();
    uint32_t* keys = (uint32_t*)(smem + SM_CAND);
    #pragma unroll
    for (int s = 0; s < 8; s++) {
        int rl = mw * 64 + (s >> 1) * 16 + (lane >> 2) + (s & 1) * 8;
        int p  = (nw * 4 + (lane & 3)) * 2;
        keys[rl * CANDS + p]     = kb1[s];
        keys[rl * CANDS + p + 1] = kb2[s];
    }
    __syncthreads();

    // ---- rescue: 4 coarsely-best of 16, exact fp32 rescore (R1 numerics) ----
    const int row = blockIdx.x * MCTA + tid;
    float zr[ZD];
    {
        const float4* zp = (const float4*)(z + (size_t)row * ZD);
        #pragma unroll
        for (int i = 0; i < ZD / 4; i++) {
            float4 v = zp[i];
            zr[4*i] = v.x; zr[4*i+1] = v.y; zr[4*i+2] = v.z; zr[4*i+3] = v.w;
        }
    }
    uint32_t used = 0;
    float bd = CUDART_INF_F;
    int   bi = KC;
    #pragma unroll
    for (int j = 0; j < 4; j++) {
        uint32_t mn = 0xFFFFFFFFu; int mp = 0;
        #pragma unroll
        for (int p = 0; p < 16; p++) {
            uint32_t k = keys[tid * CANDS + p];
            k = ((used >> p) & 1u) ? 0xFFFFFFFFu : k;
            if (k < mn) { mn = k; mp = p; }
        }
        used |= 1u << mp;
        int idx = (int)(mn & 0x7FFu);
        const float4* ep = (const float4*)(e + (size_t)idx * ZD);
        float a0=0.f,a1=0.f,a2=0.f,a3=0.f;
        #pragma unroll
        for (int i = 0; i < ZD / 4; i++) {
            float4 v = ep[i];
            a0 = fmaf(zr[4*i],   v.x, a0); a1 = fmaf(zr[4*i+1], v.y, a1);
            a2 = fmaf(zr[4*i+2], v.z, a2); a3 = fmaf(zr[4*i+3], v.w, a3);
        }
        float d = esq_s[idx] - 2.0f * ((a0 + a1) + (a2 + a3));
        if (d < bd || (d == bd && idx < bi)) { bd = d; bi = idx; }
    }

    // ---- outputs: z_q row, index, loss ----
    float lsum = 0.f;
    {
        const float4* ep = (const float4*)(e + (size_t)bi * ZD);
        float4* orow = (float4*)(out + (size_t)row * ZD);
        #pragma unroll
        for (int i = 0; i < ZD / 4; i++) {
            float4 v = ep[i];
            float dx = zr[4*i]   - v.x, dy = zr[4*i+1] - v.y;
            float dz = zr[4*i+2] - v.z, dw = zr[4*i+3] - v.w;
            lsum += dx*dx + dy*dy + dz*dz + dw*dw;
            orow[i] = v;
        }
    }
    out[(size_t)NR * ZD + row] = (float)bi;

    #pragma unroll
    for (int s = 16; s > 0; s >>= 1)
        lsum += __shfl_xor_sync(0xFFFFFFFFu, lsum, s);
    if (lane == 0) atomicAdd(&g_loss, (double)lsum);
}

__global__ void k_fin(float* __restrict__ out) {
    out[(size_t)NR * ZD + NR] = (float)(g_loss / ((double)NR * (double)ZD));
}

extern "C" void kernel_launch(void* const* d_in, const int* in_sizes, int n_in,
                              void* d_out, int out_size) {
    const float* z = (const float*)d_in[0];
    const float* e = (const float*)d_in[1];
    float* out = (float*)d_out;

    cudaFuncSetAttribute(k_main, cudaFuncAttributeMaxDynamicSharedMemorySize, SMEM_TOTAL);
    k_init<<<1, 1>>>();
    k_prep<<<(KC + 127) / 128, 128>>>(e);
    k_main<<<GRID, TPB, SMEM_TOTAL>>>(z, e, out);
    k_fin<<<1, 1>>>(out);
}

// round 13
// speedup vs baseline: 6.3094x; 1.2505x over previous
#include <cuda_runtime.h>
#include <cuda_fp16.h>
#include <math_constants.h>
#include <cstdint>

#define NR 131072
#define ZD 64
#define KC 2048
#define MCTA 128
#define NTILE 128
#define NT (KC / NTILE)   // 16
#define TPB 256
#define GRID (NR / MCTA)  // 1024
#define ROWB 144          // smem row stride (128B data + 16 pad) -> ldmatrix conflict-free

// smem layout (bytes)
#define SM_A     0            // 128 x 144 = 18432
#define SM_B     18432        // 2 x 18432
#define BTILE_B  18432
#define SM_ESQ   55296        // 2048 f32 (exact, for rescore)
#define SM_ZSQ   63488        // 128 f32
#define SM_RES   64000        // 2 x 128 x 8B rescue results
#define SMEM_TOTAL 66048
#define SM_CAND  18432        // overlays B after GEMM (needs 128*17*4 = 8704)
#define CANDS    17

__device__ __align__(16) unsigned short g_B[KC * ZD];   // fp16 codebook, K-major
__device__ float  g_esq[KC];
__device__ double g_loss;

__device__ __forceinline__ uint32_t smem_u32(const void* p) {
    uint32_t a;
    asm("{ .reg .u64 t; cvta.to.shared.u64 t, %1; cvt.u32.u64 %0, t; }" : "=r"(a) : "l"(p));
    return a;
}

#define LDMX4(r0, r1, r2, r3, a)                                              \
    asm volatile("ldmatrix.sync.aligned.m8n8.x4.shared.b16 {%0,%1,%2,%3},[%4];" \
                 : "=r"(r0), "=r"(r1), "=r"(r2), "=r"(r3) : "r"(a))

#define MMA16816(c, a0, a1, a2, a3, b0, b1)                                   \
    asm volatile("mma.sync.aligned.m16n8k16.row.col.f32.f16.f16.f32 "         \
                 "{%0,%1,%2,%3},{%4,%5,%6,%7},{%8,%9},{%0,%1,%2,%3};"         \
                 : "+f"((c)[0]), "+f"((c)[1]), "+f"((c)[2]), "+f"((c)[3])     \
                 : "r"(a0), "r"(a1), "r"(a2), "r"(a3), "r"(b0), "r"(b1))

// branchless top-2 on packed (distance|index) keys: 3 IMNMX
#define TOP2(b1, b2, k) do {                       \
    uint32_t _mx = max((b1), (k));                 \
    (b1) = min((b1), (k));                         \
    (b2) = min((b2), _mx); } while (0)

// key = (bits(d') & ~0x7FF) | idx  (d' positive: biased by z^2)
__device__ __forceinline__ uint32_t packkey(float d, int idx) {
    return (__float_as_uint(d) & 0xFFFFF800u) | (uint32_t)idx;
}

__global__ void k_init() { g_loss = 0.0; }

// fp16 codebook + exact fp32 esq (R1 accumulation order), vectorized.
__global__ void k_prep(const float* __restrict__ e) {
    int k = blockIdx.x * blockDim.x + threadIdx.x;
    if (k >= KC) return;
    const float4* er = (const float4*)(e + (size_t)k * ZD);
    uint2* br = (uint2*)(g_B + (size_t)k * ZD);
    float s0 = 0.f, s1 = 0.f, s2 = 0.f, s3 = 0.f;
    #pragma unroll
    for (int i = 0; i < 16; i++) {
        float4 v = er[i];
        s0 = fmaf(v.x, v.x, s0);
        s1 = fmaf(v.y, v.y, s1);
        s2 = fmaf(v.z, v.z, s2);
        s3 = fmaf(v.w, v.w, s3);
        __half2 p0 = __floats2half2_rn(v.x, v.y);
        __half2 p1 = __floats2half2_rn(v.z, v.w);
        uint2 o;
        o.x = *reinterpret_cast<uint32_t*>(&p0);
        o.y = *reinterpret_cast<uint32_t*>(&p1);
        br[i] = o;
    }
    g_esq[k] = (s0 + s1) + (s2 + s3);
}

__device__ __forceinline__ void prefetch_B(int t, int buf, uint32_t sb, int tid) {
    const char* src = (const char*)g_B + (size_t)t * NTILE * ZD * 2;
    uint32_t dst0 = sb + SM_B + buf * BTILE_B;
    #pragma unroll
    for (int j = 0; j < 4; j++) {
        int ch = j * TPB + tid;          // 1024 chunks of 16B
        int row = ch >> 3, c = ch & 7;
        asm volatile("cp.async.cg.shared.global [%0], [%1], 16;"
                     :: "r"(dst0 + row * ROWB + c * 16),
                        "l"(src + row * 128 + c * 16) : "memory");
    }
}

__global__ __launch_bounds__(TPB, 2)
void k_main(const float* __restrict__ z, const float* __restrict__ e,
            float* __restrict__ out) {
    extern __shared__ char smem[];
    const uint32_t sb = smem_u32(smem);
    const int tid = threadIdx.x, wid = tid >> 5, lane = tid & 31;
    const int mw = wid & 3, nw = wid >> 2;

    // ---- A: convert 128 z-rows to fp16 (2 threads/row); record z^2 ----
    {
        const int ar0 = tid >> 1, hf = tid & 1;
        const float4* zp = (const float4*)(z + (size_t)(blockIdx.x * MCTA + ar0) * ZD + hf * 32);
        char* ar = smem + SM_A + ar0 * ROWB + hf * 64;
        float zs = 0.f;
        #pragma unroll
        for (int i = 0; i < 8; i++) {
            float4 v = zp[i];
            zs += v.x * v.x + v.y * v.y + v.z * v.z + v.w * v.w;
            __half2 p0 = __floats2half2_rn(v.x, v.y);
            __half2 p1 = __floats2half2_rn(v.z, v.w);
            *(uint32_t*)(ar + 8 * i)     = *reinterpret_cast<uint32_t*>(&p0);
            *(uint32_t*)(ar + 8 * i + 4) = *reinterpret_cast<uint32_t*>(&p1);
        }
        zs += __shfl_xor_sync(0xFFFFFFFFu, zs, 1);
        if (hf == 0) ((float*)(smem + SM_ZSQ))[ar0] = zs;
    }
    // esq -> smem
    {
        float4* d = (float4*)(smem + SM_ESQ);
        const float4* s = (const float4*)g_esq;
        #pragma unroll
        for (int i = 0; i < 2; i++) d[i * TPB + tid] = s[i * TPB + tid];
    }
    prefetch_B(0, 0, sb, tid);
    asm volatile("cp.async.commit_group;" ::: "memory");

    const float* esq_s = (const float*)(smem + SM_ESQ);

    // ldmatrix lane addresses (fragment mappings verified R8-R10; M-warp tile now 32)
    const uint32_t a_l = sb + SM_A
        + (uint32_t)(mw * 32 + (lane & 7) + ((lane >> 3) & 1) * 8) * ROWB
        + (lane >> 4) * 16;
    const uint32_t b_l = sb + SM_B
        + (uint32_t)(nw * 64 + (lane & 7) + (lane >> 4) * 8) * ROWB
        + ((lane >> 3) & 1) * 16;

    uint32_t kb1[4], kb2[4];
    #pragma unroll
    for (int s = 0; s < 4; s++) { kb1[s] = 0xFFFFFFFFu; kb2[s] = 0xFFFFFFFFu; }
    float zsq[4];

    for (int t = 0; t < NT; t++) {
        asm volatile("cp.async.wait_group 0;" ::: "memory");
        __syncthreads();
        if (t == 0) {
            const float* zq = (const float*)(smem + SM_ZSQ);
            #pragma unroll
            for (int s = 0; s < 4; s++)
                zsq[s] = zq[mw * 32 + (s >> 1) * 16 + (lane >> 2) + (s & 1) * 8];
        }
        if (t + 1 < NT) {
            prefetch_B(t + 1, (t + 1) & 1, sb, tid);
            asm volatile("cp.async.commit_group;" ::: "memory");
        }
        const uint32_t bb = b_l + (t & 1) * BTILE_B;
        const int colb0 = t * NTILE + nw * 64 + (lane & 3) * 2;

        #pragma unroll
        for (int h = 0; h < 2; h++) {
            float acc[2][4][4];
            #pragma unroll
            for (int f = 0; f < 2; f++)
                #pragma unroll
                for (int g = 0; g < 4; g++)
                    #pragma unroll
                    for (int q = 0; q < 4; q++) acc[f][g][q] = 0.f;

            #pragma unroll
            for (int ks = 0; ks < 4; ks++) {
                uint32_t bx[4], by[4];
                LDMX4(bx[0], by[0], bx[1], by[1], bb + (2 * h + 0) * 16 * ROWB + ks * 32);
                LDMX4(bx[2], by[2], bx[3], by[3], bb + (2 * h + 1) * 16 * ROWB + ks * 32);
                #pragma unroll
                for (int f = 0; f < 2; f++) {
                    uint32_t a0, a1, a2, a3;
                    LDMX4(a0, a1, a2, a3, a_l + f * 16 * ROWB + ks * 32);
                    #pragma unroll
                    for (int g = 0; g < 4; g++)
                        MMA16816(acc[f][g], a0, a1, a2, a3, bx[g], by[g]);
                }
            }

            const int colb = colb0 + h * 32;
            #pragma unroll
            for (int g = 0; g < 4; g++) {
                const int col = colb + g * 8;
                const float e0 = esq_s[col], e1 = esq_s[col + 1];
                #pragma unroll
                for (int f = 0; f < 2; f++) {
                    const int s0 = 2 * f, s1 = 2 * f + 1;
                    float d00 = fmaf(-2.f, acc[f][g][0], e0) + zsq[s0];
                    float d01 = fmaf(-2.f, acc[f][g][1], e1) + zsq[s0];
                    float d10 = fmaf(-2.f, acc[f][g][2], e0) + zsq[s1];
                    float d11 = fmaf(-2.f, acc[f][g][3], e1) + zsq[s1];
                    TOP2(kb1[s0], kb2[s0], packkey(d00, col));
                    TOP2(kb1[s0], kb2[s0], packkey(d01, col + 1));
                    TOP2(kb1[s1], kb2[s1], packkey(d10, col));
                    TOP2(kb1[s1], kb2[s1], packkey(d11, col + 1));
                }
            }
        }
    }

    // ---- publish candidate keys (overlay B region) ----
    __syncthreads();
    uint32_t* keys = (uint32_t*)(smem + SM_CAND);
    #pragma unroll
    for (int s = 0; s < 4; s++) {
        int rl = mw * 32 + (s >> 1) * 16 + (lane >> 2) + (s & 1) * 8;
        int p  = (nw * 4 + (lane & 3)) * 2;
        keys[rl * CANDS + p]     = kb1[s];
        keys[rl * CANDS + p + 1] = kb2[s];
    }
    __syncthreads();

    // ---- rescue: 2 threads/row, each rescores 2 of the 4 coarsely-best ----
    const int r  = tid & 127, hf2 = tid >> 7;
    const int row = blockIdx.x * MCTA + r;
    float zr[ZD];
    {
        const float4* zp = (const float4*)(z + (size_t)row * ZD);
        #pragma unroll
        for (int i = 0; i < ZD / 4; i++) {
            float4 v = zp[i];
            zr[4*i] = v.x; zr[4*i+1] = v.y; zr[4*i+2] = v.z; zr[4*i+3] = v.w;
        }
    }
    uint32_t used = 0;
    float bd = CUDART_INF_F;
    int   bi = KC;
    #pragma unroll
    for (int j = 0; j < 4; j++) {
        uint32_t mn = 0xFFFFFFFFu; int mp = 0;
        #pragma unroll
        for (int p = 0; p < 16; p++) {
            uint32_t k = keys[r * CANDS + p];
            k = ((used >> p) & 1u) ? 0xFFFFFFFFu : k;
            if (k < mn) { mn = k; mp = p; }
        }
        used |= 1u << mp;
        if ((j >> 1) == hf2) {                 // this thread rescores ranks {2hf2, 2hf2+1}
            int idx = (int)(mn & 0x7FFu);
            const float4* ep = (const float4*)(e + (size_t)idx * ZD);
            float a0=0.f,a1=0.f,a2=0.f,a3=0.f;
            #pragma unroll
            for (int i = 0; i < ZD / 4; i++) {
                float4 v = ep[i];
                a0 = fmaf(zr[4*i],   v.x, a0); a1 = fmaf(zr[4*i+1], v.y, a1);
                a2 = fmaf(zr[4*i+2], v.z, a2); a3 = fmaf(zr[4*i+3], v.w, a3);
            }
            float d = esq_s[idx] - 2.0f * ((a0 + a1) + (a2 + a3));
            if (d < bd || (d == bd && idx < bi)) { bd = d; bi = idx; }
        }
    }
    {
        float* resd = (float*)(smem + SM_RES);
        int*   resi = (int*)(smem + SM_RES + 2 * MCTA * 4);
        resd[hf2 * MCTA + r] = bd;
        resi[hf2 * MCTA + r] = bi;
    }
    __syncthreads();

    // ---- combine halves + outputs (threads 0..127) ----
    if (tid < MCTA) {
        const float* resd = (const float*)(smem + SM_RES);
        const int*   resi = (const int*)(smem + SM_RES + 2 * MCTA * 4);
        float d0 = resd[r], d1 = resd[MCTA + r];
        int   i0 = resi[r], i1 = resi[MCTA + r];
        int win = (d1 < d0 || (d1 == d0 && i1 < i0)) ? i1 : i0;

        float lsum = 0.f;
        const float4* ep = (const float4*)(e + (size_t)win * ZD);
        float4* orow = (float4*)(out + (size_t)row * ZD);
        #pragma unroll
        for (int i = 0; i < ZD / 4; i++) {
            float4 v = ep[i];
            float dx = zr[4*i]   - v.x, dy = zr[4*i+1] - v.y;
            float dz = zr[4*i+2] - v.z, dw = zr[4*i+3] - v.w;
            lsum += dx*dx + dy*dy + dz*dz + dw*dw;
            orow[i] = v;
        }
        out[(size_t)NR * ZD + row] = (float)win;

        #pragma unroll
        for (int s = 16; s > 0; s >>= 1)
            lsum += __shfl_xor_sync(0xFFFFFFFFu, lsum, s);
        if (lane == 0) atomicAdd(&g_loss, (double)lsum);
    }
}

__global__ void k_fin(float* __restrict__ out) {
    out[(size_t)NR * ZD + NR] = (float)(g_loss / ((double)NR * (double)ZD));
}

extern "C" void kernel_launch(void* const* d_in, const int* in_sizes, int n_in,
                              void* d_out, int out_size) {
    const float* z = (const float*)d_in[0];
    const float* e = (const float*)d_in[1];
    float* out = (float*)d_out;

    cudaFuncSetAttribute(k_main, cudaFuncAttributeMaxDynamicSharedMemorySize, SMEM_TOTAL);
    k_init<<<1, 1>>>();
    k_prep<<<(KC + 127) / 128, 128>>>(e);
    k_main<<<GRID, TPB, SMEM_TOTAL>>>(z, e, out);
    k_fin<<<1, 1>>>(out);
}

// round 14
// speedup vs baseline: 6.4173x; 1.0171x over previous
#include <cuda_runtime.h>
#include <cuda_fp16.h>
#include <math_constants.h>
#include <cstdint>

#define NR 131072
#define ZD 64
#define KC 2048
#define MCTA 128
#define NTILE 128
#define NT (KC / NTILE)   // 16
#define TPB 256
#define GRID (NR / MCTA)  // 1024
#define ROWB 144          // smem row stride (128B data + 16 pad) -> ldmatrix conflict-free

// smem layout (bytes) — 72KB/CTA so 3 CTAs fit per SM
#define SM_A     0            // 128 x 144 = 18432
#define SM_B     18432        // 2 x 18432
#define BTILE_B  18432
#define SM_ESQB  55296        // 2048 f32 biased (+256) for epilogue
#define SM_ESQ   63488        // 2048 f32 exact for rescore
#define SM_RES   71680        // 2 x 128 x 8B rescue results
#define SMEM_TOTAL 73728
#define SM_CAND  18432        // overlays B after GEMM (needs 128*17*4 = 8704)
#define CANDS    17

#define DBIAS 256.0f

__device__ __align__(16) unsigned short g_B[KC * ZD];   // fp16 codebook, K-major
__device__ float  g_esq[KC];
__device__ double g_loss;

__device__ __forceinline__ uint32_t smem_u32(const void* p) {
    uint32_t a;
    asm("{ .reg .u64 t; cvta.to.shared.u64 t, %1; cvt.u32.u64 %0, t; }" : "=r"(a) : "l"(p));
    return a;
}

#define LDMX4(r0, r1, r2, r3, a)                                              \
    asm volatile("ldmatrix.sync.aligned.m8n8.x4.shared.b16 {%0,%1,%2,%3},[%4];" \
                 : "=r"(r0), "=r"(r1), "=r"(r2), "=r"(r3) : "r"(a))

#define MMA16816(c, a0, a1, a2, a3, b0, b1)                                   \
    asm volatile("mma.sync.aligned.m16n8k16.row.col.f32.f16.f16.f32 "         \
                 "{%0,%1,%2,%3},{%4,%5,%6,%7},{%8,%9},{%0,%1,%2,%3};"         \
                 : "+f"((c)[0]), "+f"((c)[1]), "+f"((c)[2]), "+f"((c)[3])     \
                 : "r"(a0), "r"(a1), "r"(a2), "r"(a3), "r"(b0), "r"(b1))

// branchless top-2 on packed (distance|index) keys: 3 IMNMX
#define TOP2(b1, b2, k) do {                       \
    uint32_t _mx = max((b1), (k));                 \
    (b1) = min((b1), (k));                         \
    (b2) = min((b2), _mx); } while (0)

// key = (bits(d') & ~0x7FF) | idx  (d' positive via +256 bias in esqB)
__device__ __forceinline__ uint32_t packkey(float d, int idx) {
    return (__float_as_uint(d) & 0xFFFFF800u) | (uint32_t)idx;
}

__global__ void k_init() { g_loss = 0.0; }

// fp16 codebook + exact fp32 esq (R1 accumulation order), vectorized.
__global__ void k_prep(const float* __restrict__ e) {
    int k = blockIdx.x * blockDim.x + threadIdx.x;
    if (k >= KC) return;
    const float4* er = (const float4*)(e + (size_t)k * ZD);
    uint2* br = (uint2*)(g_B + (size_t)k * ZD);
    float s0 = 0.f, s1 = 0.f, s2 = 0.f, s3 = 0.f;
    #pragma unroll
    for (int i = 0; i < 16; i++) {
        float4 v = er[i];
        s0 = fmaf(v.x, v.x, s0);
        s1 = fmaf(v.y, v.y, s1);
        s2 = fmaf(v.z, v.z, s2);
        s3 = fmaf(v.w, v.w, s3);
        __half2 p0 = __floats2half2_rn(v.x, v.y);
        __half2 p1 = __floats2half2_rn(v.z, v.w);
        uint2 o;
        o.x = *reinterpret_cast<uint32_t*>(&p0);
        o.y = *reinterpret_cast<uint32_t*>(&p1);
        br[i] = o;
    }
    g_esq[k] = (s0 + s1) + (s2 + s3);
}

__device__ __forceinline__ void prefetch_B(int t, int buf, uint32_t sb, int tid) {
    const char* src = (const char*)g_B + (size_t)t * NTILE * ZD * 2;
    uint32_t dst0 = sb + SM_B + buf * BTILE_B;
    #pragma unroll
    for (int j = 0; j < 4; j++) {
        int ch = j * TPB + tid;          // 1024 chunks of 16B
        int row = ch >> 3, c = ch & 7;
        asm volatile("cp.async.cg.shared.global [%0], [%1], 16;"
                     :: "r"(dst0 + row * ROWB + c * 16),
                        "l"(src + row * 128 + c * 16) : "memory");
    }
}

__global__ __launch_bounds__(TPB, 3)
void k_main(const float* __restrict__ z, const float* __restrict__ e,
            float* __restrict__ out) {
    extern __shared__ char smem[];
    const uint32_t sb = smem_u32(smem);
    const int tid = threadIdx.x, wid = tid >> 5, lane = tid & 31;
    const int mw = wid & 3, nw = wid >> 2;

    // ---- A: convert 128 z-rows to fp16 (2 threads/row) ----
    {
        const int ar0 = tid >> 1, hf = tid & 1;
        const float4* zp = (const float4*)(z + (size_t)(blockIdx.x * MCTA + ar0) * ZD + hf * 32);
        char* ar = smem + SM_A + ar0 * ROWB + hf * 64;
        #pragma unroll
        for (int i = 0; i < 8; i++) {
            float4 v = zp[i];
            __half2 p0 = __floats2half2_rn(v.x, v.y);
            __half2 p1 = __floats2half2_rn(v.z, v.w);
            *(uint32_t*)(ar + 8 * i)     = *reinterpret_cast<uint32_t*>(&p0);
            *(uint32_t*)(ar + 8 * i + 4) = *reinterpret_cast<uint32_t*>(&p1);
        }
    }
    // esq -> smem: biased copy (epilogue) + exact copy (rescore)
    {
        float4* db = (float4*)(smem + SM_ESQB);
        float4* dx = (float4*)(smem + SM_ESQ);
        const float4* s = (const float4*)g_esq;
        #pragma unroll
        for (int i = 0; i < 2; i++) {
            float4 v = s[i * TPB + tid];
            dx[i * TPB + tid] = v;
            v.x += DBIAS; v.y += DBIAS; v.z += DBIAS; v.w += DBIAS;
            db[i * TPB + tid] = v;
        }
    }
    prefetch_B(0, 0, sb, tid);
    asm volatile("cp.async.commit_group;" ::: "memory");

    const float* esqb_s = (const float*)(smem + SM_ESQB);
    const float* esq_s  = (const float*)(smem + SM_ESQ);

    // ldmatrix lane addresses (fragment mappings verified R8-R13)
    const uint32_t a_l = sb + SM_A
        + (uint32_t)(mw * 32 + (lane & 7) + ((lane >> 3) & 1) * 8) * ROWB
        + (lane >> 4) * 16;
    const uint32_t b_l = sb + SM_B
        + (uint32_t)(nw * 64 + (lane & 7) + (lane >> 4) * 8) * ROWB
        + ((lane >> 3) & 1) * 16;

    uint32_t kb1[4], kb2[4];
    #pragma unroll
    for (int s = 0; s < 4; s++) { kb1[s] = 0xFFFFFFFFu; kb2[s] = 0xFFFFFFFFu; }

    for (int t = 0; t < NT; t++) {
        asm volatile("cp.async.wait_group 0;" ::: "memory");
        __syncthreads();
        if (t + 1 < NT) {
            prefetch_B(t + 1, (t + 1) & 1, sb, tid);
            asm volatile("cp.async.commit_group;" ::: "memory");
        }
        const uint32_t bb = b_l + (t & 1) * BTILE_B;
        const int colb0 = t * NTILE + nw * 64 + (lane & 3) * 2;

        #pragma unroll
        for (int h = 0; h < 2; h++) {
            float acc[2][4][4];
            #pragma unroll
            for (int f = 0; f < 2; f++)
                #pragma unroll
                for (int g = 0; g < 4; g++)
                    #pragma unroll
                    for (int q = 0; q < 4; q++) acc[f][g][q] = 0.f;

            #pragma unroll
            for (int ks = 0; ks < 4; ks++) {
                uint32_t bx[4], by[4];
                LDMX4(bx[0], by[0], bx[1], by[1], bb + (2 * h + 0) * 16 * ROWB + ks * 32);
                LDMX4(bx[2], by[2], bx[3], by[3], bb + (2 * h + 1) * 16 * ROWB + ks * 32);
                #pragma unroll
                for (int f = 0; f < 2; f++) {
                    uint32_t a0, a1, a2, a3;
                    LDMX4(a0, a1, a2, a3, a_l + f * 16 * ROWB + ks * 32);
                    #pragma unroll
                    for (int g = 0; g < 4; g++)
                        MMA16816(acc[f][g], a0, a1, a2, a3, bx[g], by[g]);
                }
            }

            const int colb = colb0 + h * 32;
            #pragma unroll
            for (int g = 0; g < 4; g++) {
                const int col = colb + g * 8;
                const float e0 = esqb_s[col], e1 = esqb_s[col + 1];
                #pragma unroll
                for (int f = 0; f < 2; f++) {
                    const int s0 = 2 * f, s1 = 2 * f + 1;
                    float d00 = fmaf(-2.f, acc[f][g][0], e0);
                    float d01 = fmaf(-2.f, acc[f][g][1], e1);
                    float d10 = fmaf(-2.f, acc[f][g][2], e0);
                    float d11 = fmaf(-2.f, acc[f][g][3], e1);
                    TOP2(kb1[s0], kb2[s0], packkey(d00, col));
                    TOP2(kb1[s0], kb2[s0], packkey(d01, col + 1));
                    TOP2(kb1[s1], kb2[s1], packkey(d10, col));
                    TOP2(kb1[s1], kb2[s1], packkey(d11, col + 1));
                }
            }
        }
    }

    // ---- publish candidate keys (overlay B region) ----
    __syncthreads();
    uint32_t* keys = (uint32_t*)(smem + SM_CAND);
    #pragma unroll
    for (int s = 0; s < 4; s++) {
        int rl = mw * 32 + (s >> 1) * 16 + (lane >> 2) + (s & 1) * 8;
        int p  = (nw * 4 + (lane & 3)) * 2;
        keys[rl * CANDS + p]     = kb1[s];
        keys[rl * CANDS + p + 1] = kb2[s];
    }
    __syncthreads();

    // ---- rescue: 2 threads/row, each rescores 2 of the 4 coarsely-best ----
    const int r  = tid & 127, hf2 = tid >> 7;
    const int row = blockIdx.x * MCTA + r;
    float zr[ZD];
    {
        const float4* zp = (const float4*)(z + (size_t)row * ZD);
        #pragma unroll
        for (int i = 0; i < ZD / 4; i++) {
            float4 v = zp[i];
            zr[4*i] = v.x; zr[4*i+1] = v.y; zr[4*i+2] = v.z; zr[4*i+3] = v.w;
        }
    }
    uint32_t used = 0;
    float bd = CUDART_INF_F;
    int   bi = KC;
    #pragma unroll
    for (int j = 0; j < 4; j++) {
        uint32_t mn = 0xFFFFFFFFu; int mp = 0;
        #pragma unroll
        for (int p = 0; p < 16; p++) {
            uint32_t k = keys[r * CANDS + p];
            k = ((used >> p) & 1u) ? 0xFFFFFFFFu : k;
            if (k < mn) { mn = k; mp = p; }
        }
        used |= 1u << mp;
        if ((j >> 1) == hf2) {                 // this thread rescores ranks {2hf2, 2hf2+1}
            int idx = (int)(mn & 0x7FFu);
            const float4* ep = (const float4*)(e + (size_t)idx * ZD);
            float a0=0.f,a1=0.f,a2=0.f,a3=0.f;
            #pragma unroll
            for (int i = 0; i < ZD / 4; i++) {
                float4 v = ep[i];
                a0 = fmaf(zr[4*i],   v.x, a0); a1 = fmaf(zr[4*i+1], v.y, a1);
                a2 = fmaf(zr[4*i+2], v.z, a2); a3 = fmaf(zr[4*i+3], v.w, a3);
            }
            float d = esq_s[idx] - 2.0f * ((a0 + a1) + (a2 + a3));
            if (d < bd || (d == bd && idx < bi)) { bd = d; bi = idx; }
        }
    }
    {
        float* resd = (float*)(smem + SM_RES);
        int*   resi = (int*)(smem + SM_RES + 2 * MCTA * 4);
        resd[hf2 * MCTA + r] = bd;
        resi[hf2 * MCTA + r] = bi;
    }
    __syncthreads();

    // ---- combine halves + outputs (threads 0..127) ----
    if (tid < MCTA) {
        const float* resd = (const float*)(smem + SM_RES);
        const int*   resi = (const int*)(smem + SM_RES + 2 * MCTA * 4);
        float d0 = resd[r], d1 = resd[MCTA + r];
        int   i0 = resi[r], i1 = resi[MCTA + r];
        int win = (d1 < d0 || (d1 == d0 && i1 < i0)) ? i1 : i0;

        float lsum = 0.f;
        const float4* ep = (const float4*)(e + (size_t)win * ZD);
        float4* orow = (float4*)(out + (size_t)row * ZD);
        #pragma unroll
        for (int i = 0; i < ZD / 4; i++) {
            float4 v = ep[i];
            float dx = zr[4*i]   - v.x, dy = zr[4*i+1] - v.y;
            float dz = zr[4*i+2] - v.z, dw = zr[4*i+3] - v.w;
            lsum += dx*dx + dy*dy + dz*dz + dw*dw;
            orow[i] = v;
        }
        out[(size_t)NR * ZD + row] = (float)win;

        #pragma unroll
        for (int s = 16; s > 0; s >>= 1)
            lsum += __shfl_xor_sync(0xFFFFFFFFu, lsum, s);
        if (lane == 0) atomicAdd(&g_loss, (double)lsum);
    }
}

__global__ void k_fin(float* __restrict__ out) {
    out[(size_t)NR * ZD + NR] = (float)(g_loss / ((double)NR * (double)ZD));
}

extern "C" void kernel_launch(void* const* d_in, const int* in_sizes, int n_in,
                              void* d_out, int out_size) {
    const float* z = (const float*)d_in[0];
    const float* e = (const float*)d_in[1];
    float* out = (float*)d_out;

    cudaFuncSetAttribute(k_main, cudaFuncAttributeMaxDynamicSharedMemorySize, SMEM_TOTAL);
    k_init<<<1, 1>>>();
    k_prep<<<(KC + 127) / 128, 128>>>(e);
    k_main<<<GRID, TPB, SMEM_TOTAL>>>(z, e, out);
    k_fin<<<1, 1>>>(out);
}

// round 15
// speedup vs baseline: 6.7082x; 1.0453x over previous
#include <cuda_runtime.h>
#include <cuda_fp16.h>
#include <math_constants.h>
#include <cstdint>

#define NR 131072
#define ZD 64
#define KC 2048
#define MCTA 128
#define NTILE 128
#define NT (KC / NTILE)   // 16
#define TPB 256
#define GRID (NR / MCTA)  // 1024
#define ROWB 144          // smem row stride (128B data + 16 pad) -> ldmatrix conflict-free

// smem layout (bytes) — 72KB/CTA, 3 CTAs/SM
#define SM_A     0            // 128 x 144 = 18432
#define SM_B     18432        // 2 x 18432
#define BTILE_B  18432
#define SM_ESQB  55296        // 2048 f32 biased (+256) for epilogue
#define SM_ESQ   63488        // 2048 f32 exact for rescore
#define SM_RES   71680        // 2 x 128 x 8B rescue results
#define SMEM_TOTAL 73728
#define SM_CAND  18432        // overlays B after GEMM (needs 8704)
#define CANDS    17

#define DBIAS 256.0f

__device__ __align__(16) unsigned short g_B[KC * ZD];   // fp16 codebook, K-major
__device__ float  g_esq[KC];
__device__ double g_loss;
__device__ int    g_done;

__device__ __forceinline__ uint32_t smem_u32(const void* p) {
    uint32_t a;
    asm("{ .reg .u64 t; cvta.to.shared.u64 t, %1; cvt.u32.u64 %0, t; }" : "=r"(a) : "l"(p));
    return a;
}

#define LDMX4(r0, r1, r2, r3, a)                                              \
    asm volatile("ldmatrix.sync.aligned.m8n8.x4.shared.b16 {%0,%1,%2,%3},[%4];" \
                 : "=r"(r0), "=r"(r1), "=r"(r2), "=r"(r3) : "r"(a))

// fp16-accumulator HMMA: D,C packed half2 pairs {c0c1, c2c3}
#define MMA16816H(c, a0, a1, a2, a3, b0, b1)                                  \
    asm volatile("mma.sync.aligned.m16n8k16.row.col.f16.f16.f16.f16 "         \
                 "{%0,%1},{%2,%3,%4,%5},{%6,%7},{%0,%1};"                     \
                 : "+r"((c)[0]), "+r"((c)[1])                                 \
                 : "r"(a0), "r"(a1), "r"(a2), "r"(a3), "r"(b0), "r"(b1))

// branchless top-2 on packed (distance|index) keys: 3 IMNMX
#define TOP2(b1, b2, k) do {                       \
    uint32_t _mx = max((b1), (k));                 \
    (b1) = min((b1), (k));                         \
    (b2) = min((b2), _mx); } while (0)

// key = (bits(d') & ~0x7FF) | idx  (d' positive via +256 bias in esqB)
__device__ __forceinline__ uint32_t packkey(float d, int idx) {
    return (__float_as_uint(d) & 0xFFFFF800u) | (uint32_t)idx;
}

// fp16 codebook + exact fp32 esq (R1 accumulation order); also resets accumulators.
__global__ void k_prep(const float* __restrict__ e) {
    if (blockIdx.x == 0 && threadIdx.x == 0) { g_loss = 0.0; g_done = 0; }
    int k = blockIdx.x * blockDim.x + threadIdx.x;
    if (k >= KC) return;
    const float4* er = (const float4*)(e + (size_t)k * ZD);
    uint2* br = (uint2*)(g_B + (size_t)k * ZD);
    float s0 = 0.f, s1 = 0.f, s2 = 0.f, s3 = 0.f;
    #pragma unroll
    for (int i = 0; i < 16; i++) {
        float4 v = er[i];
        s0 = fmaf(v.x, v.x, s0);
        s1 = fmaf(v.y, v.y, s1);
        s2 = fmaf(v.z, v.z, s2);
        s3 = fmaf(v.w, v.w, s3);
        __half2 p0 = __floats2half2_rn(v.x, v.y);
        __half2 p1 = __floats2half2_rn(v.z, v.w);
        uint2 o;
        o.x = *reinterpret_cast<uint32_t*>(&p0);
        o.y = *reinterpret_cast<uint32_t*>(&p1);
        br[i] = o;
    }
    g_esq[k] = (s0 + s1) + (s2 + s3);
}

__device__ __forceinline__ void prefetch_B(int t, int buf, uint32_t sb, int tid) {
    const char* src = (const char*)g_B + (size_t)t * NTILE * ZD * 2;
    uint32_t dst0 = sb + SM_B + buf * BTILE_B;
    #pragma unroll
    for (int j = 0; j < 4; j++) {
        int ch = j * TPB + tid;          // 1024 chunks of 16B
        int row = ch >> 3, c = ch & 7;
        asm volatile("cp.async.cg.shared.global [%0], [%1], 16;"
                     :: "r"(dst0 + row * ROWB + c * 16),
                        "l"(src + row * 128 + c * 16) : "memory");
    }
}

__global__ __launch_bounds__(TPB, 3)
void k_main(const float* __restrict__ z, const float* __restrict__ e,
            float* __restrict__ out) {
    extern __shared__ char smem[];
    const uint32_t sb = smem_u32(smem);
    const int tid = threadIdx.x, wid = tid >> 5, lane = tid & 31;
    const int mw = wid & 3, nw = wid >> 2;

    // ---- A: convert 128 z-rows to fp16 (2 threads/row) ----
    {
        const int ar0 = tid >> 1, hf = tid & 1;
        const float4* zp = (const float4*)(z + (size_t)(blockIdx.x * MCTA + ar0) * ZD + hf * 32);
        char* ar = smem + SM_A + ar0 * ROWB + hf * 64;
        #pragma unroll
        for (int i = 0; i < 8; i++) {
            float4 v = zp[i];
            __half2 p0 = __floats2half2_rn(v.x, v.y);
            __half2 p1 = __floats2half2_rn(v.z, v.w);
            *(uint32_t*)(ar + 8 * i)     = *reinterpret_cast<uint32_t*>(&p0);
            *(uint32_t*)(ar + 8 * i + 4) = *reinterpret_cast<uint32_t*>(&p1);
        }
    }
    // esq -> smem: biased copy (epilogue) + exact copy (rescore)
    {
        float4* db = (float4*)(smem + SM_ESQB);
        float4* dx = (float4*)(smem + SM_ESQ);
        const float4* s = (const float4*)g_esq;
        #pragma unroll
        for (int i = 0; i < 2; i++) {
            float4 v = s[i * TPB + tid];
            dx[i * TPB + tid] = v;
            v.x += DBIAS; v.y += DBIAS; v.z += DBIAS; v.w += DBIAS;
            db[i * TPB + tid] = v;
        }
    }
    prefetch_B(0, 0, sb, tid);
    asm volatile("cp.async.commit_group;" ::: "memory");

    const float* esqb_s = (const float*)(smem + SM_ESQB);
    const float* esq_s  = (const float*)(smem + SM_ESQ);

    // ldmatrix lane addresses (fragment mappings verified R8-R14)
    const uint32_t a_l = sb + SM_A
        + (uint32_t)(mw * 32 + (lane & 7) + ((lane >> 3) & 1) * 8) * ROWB
        + (lane >> 4) * 16;
    const uint32_t b_l = sb + SM_B
        + (uint32_t)(nw * 64 + (lane & 7) + (lane >> 4) * 8) * ROWB
        + ((lane >> 3) & 1) * 16;

    uint32_t kb1[4], kb2[4];
    #pragma unroll
    for (int s = 0; s < 4; s++) { kb1[s] = 0xFFFFFFFFu; kb2[s] = 0xFFFFFFFFu; }

    for (int t = 0; t < NT; t++) {
        asm volatile("cp.async.wait_group 0;" ::: "memory");
        __syncthreads();
        if (t + 1 < NT) {
            prefetch_B(t + 1, (t + 1) & 1, sb, tid);
            asm volatile("cp.async.commit_group;" ::: "memory");
        }
        const uint32_t bb = b_l + (t & 1) * BTILE_B;
        const int colb0 = t * NTILE + nw * 64 + (lane & 3) * 2;

        uint32_t acc[2][8][2];
        #pragma unroll
        for (int f = 0; f < 2; f++)
            #pragma unroll
            for (int g = 0; g < 8; g++) { acc[f][g][0] = 0u; acc[f][g][1] = 0u; }

        #pragma unroll
        for (int ks = 0; ks < 4; ks++) {
            uint32_t bx[8], by[8];
            #pragma unroll
            for (int q = 0; q < 4; q++)
                LDMX4(bx[2 * q], by[2 * q], bx[2 * q + 1], by[2 * q + 1],
                      bb + q * 16 * ROWB + ks * 32);
            #pragma unroll
            for (int f = 0; f < 2; f++) {
                uint32_t a0, a1, a2, a3;
                LDMX4(a0, a1, a2, a3, a_l + f * 16 * ROWB + ks * 32);
                #pragma unroll
                for (int g = 0; g < 8; g++)
                    MMA16816H(acc[f][g], a0, a1, a2, a3, bx[g], by[g]);
            }
        }

        #pragma unroll
        for (int g = 0; g < 8; g++) {
            const int col = colb0 + g * 8;
            const float e0 = esqb_s[col], e1 = esqb_s[col + 1];
            #pragma unroll
            for (int f = 0; f < 2; f++) {
                const int s0 = 2 * f, s1 = 2 * f + 1;
                float2 v01 = __half22float2(*reinterpret_cast<__half2*>(&acc[f][g][0]));
                float2 v23 = __half22float2(*reinterpret_cast<__half2*>(&acc[f][g][1]));
                float d00 = fmaf(-2.f, v01.x, e0);
                float d01 = fmaf(-2.f, v01.y, e1);
                float d10 = fmaf(-2.f, v23.x, e0);
                float d11 = fmaf(-2.f, v23.y, e1);
                TOP2(kb1[s0], kb2[s0], packkey(d00, col));
                TOP2(kb1[s0], kb2[s0], packkey(d01, col + 1));
                TOP2(kb1[s1], kb2[s1], packkey(d10, col));
                TOP2(kb1[s1], kb2[s1], packkey(d11, col + 1));
            }
        }
    }

    // ---- publish candidate keys (overlay B region) ----
    __syncthreads();
    uint32_t* keys = (uint32_t*)(smem + SM_CAND);
    #pragma unroll
    for (int s = 0; s < 4; s++) {
        int rl = mw * 32 + (s >> 1) * 16 + (lane >> 2) + (s & 1) * 8;
        int p  = (nw * 4 + (lane & 3)) * 2;
        keys[rl * CANDS + p]     = kb1[s];
        keys[rl * CANDS + p + 1] = kb2[s];
    }
    __syncthreads();

    // ---- rescue: 2 threads/row, each rescores 2 of the 4 coarsely-best ----
    const int r  = tid & 127, hf2 = tid >> 7;
    const int row = blockIdx.x * MCTA + r;
    float zr[ZD];
    {
        const float4* zp = (const float4*)(z + (size_t)row * ZD);
        #pragma unroll
        for (int i = 0; i < ZD / 4; i++) {
            float4 v = zp[i];
            zr[4*i] = v.x; zr[4*i+1] = v.y; zr[4*i+2] = v.z; zr[4*i+3] = v.w;
        }
    }
    uint32_t used = 0;
    float bd = CUDART_INF_F;
    int   bi = KC;
    #pragma unroll
    for (int j = 0; j < 4; j++) {
        uint32_t mn = 0xFFFFFFFFu; int mp = 0;
        #pragma unroll
        for (int p = 0; p < 16; p++) {
            uint32_t k = keys[r * CANDS + p];
            k = ((used >> p) & 1u) ? 0xFFFFFFFFu : k;
            if (k < mn) { mn = k; mp = p; }
        }
        used |= 1u << mp;
        if ((j >> 1) == hf2) {                 // this thread rescores ranks {2hf2, 2hf2+1}
            int idx = (int)(mn & 0x7FFu);
            const float4* ep = (const float4*)(e + (size_t)idx * ZD);
            float a0=0.f,a1=0.f,a2=0.f,a3=0.f;
            #pragma unroll
            for (int i = 0; i < ZD / 4; i++) {
                float4 v = ep[i];
                a0 = fmaf(zr[4*i],   v.x, a0); a1 = fmaf(zr[4*i+1], v.y, a1);
                a2 = fmaf(zr[4*i+2], v.z, a2); a3 = fmaf(zr[4*i+3], v.w, a3);
            }
            float d = esq_s[idx] - 2.0f * ((a0 + a1) + (a2 + a3));
            if (d < bd || (d == bd && idx < bi)) { bd = d; bi = idx; }
        }
    }
    {
        float* resd = (float*)(smem + SM_RES);
        int*   resi = (int*)(smem + SM_RES + 2 * MCTA * 4);
        resd[hf2 * MCTA + r] = bd;
        resi[hf2 * MCTA + r] = bi;
    }
    __syncthreads();

    // ---- combine halves + outputs (threads 0..127) ----
    if (tid < MCTA) {
        const float* resd = (const float*)(smem + SM_RES);
        const int*   resi = (const int*)(smem + SM_RES + 2 * MCTA * 4);
        float d0 = resd[r], d1 = resd[MCTA + r];
        int   i0 = resi[r], i1 = resi[MCTA + r];
        int win = (d1 < d0 || (d1 == d0 && i1 < i0)) ? i1 : i0;

        float lsum = 0.f;
        const float4* ep = (const float4*)(e + (size_t)win * ZD);
        float4* orow = (float4*)(out + (size_t)row * ZD);
        #pragma unroll
        for (int i = 0; i < ZD / 4; i++) {
            float4 v = ep[i];
            float dx = zr[4*i]   - v.x, dy = zr[4*i+1] - v.y;
            float dz = zr[4*i+2] - v.z, dw = zr[4*i+3] - v.w;
            lsum += dx*dx + dy*dy + dz*dz + dw*dw;
            orow[i] = v;
        }
        out[(size_t)NR * ZD + row] = (float)win;

        #pragma unroll
        for (int s = 16; s > 0; s >>= 1)
            lsum += __shfl_xor_sync(0xFFFFFFFFu, lsum, s);
        if (lane == 0) atomicAdd(&g_loss, (double)lsum);
    }

    // ---- last CTA finalizes the loss (replaces k_fin) ----
    __syncthreads();
    if (tid == 0) {
        __threadfence();
        int done = atomicAdd(&g_done, 1);
        if (done == GRID - 1)
            out[(size_t)NR * ZD + NR] = (float)(g_loss / ((double)NR * (double)ZD));
    }
}

extern "C" void kernel_launch(void* const* d_in, const int* in_sizes, int n_in,
                              void* d_out, int out_size) {
    const float* z = (const float*)d_in[0];
    const float* e = (const float*)d_in[1];
    float* out = (float*)d_out;

    cudaFuncSetAttribute(k_main, cudaFuncAttributeMaxDynamicSharedMemorySize, SMEM_TOTAL);
    k_prep<<<(KC + 127) / 128, 128>>>(e);
    k_main<<<GRID, TPB, SMEM_TOTAL>>>(z, e, out);
}

// round 16
// speedup vs baseline: 6.7766x; 1.0102x over previous
#include <cuda_runtime.h>
#include <cuda_fp16.h>
#include <math_constants.h>
#include <cstdint>

#define NR 131072
#define ZD 64
#define KC 2048
#define MCTA 128
#define NTILE 128
#define NT (KC / NTILE)   // 16
#define TPB 256
#define GRID (NR / MCTA)  // 1024
#define ROWB 144          // smem row stride (128B data + 16 pad) -> ldmatrix conflict-free

// smem layout (bytes)
#define SM_A     0            // 128 x 144 = 18432
#define SM_B     18432        // 2 x 18432
#define BTILE_B  18432
#define SM_ESQB  55296        // 2048 f32 biased (+256) for epilogue
#define SM_ESQ   63488        // 2048 f32 exact for rescore
#define SM_RES   71680        // 2 x 128 x 8B rescue results
#define SMEM_TOTAL 73728
#define SM_CAND  18432        // overlays B after GEMM (needs 8704)
#define CANDS    17

#define DBIAS 256.0f

__device__ __align__(16) unsigned short g_B[KC * ZD];   // fp16 codebook, K-major
__device__ float  g_esq[KC];
__device__ double g_loss;
__device__ int    g_done;

__device__ __forceinline__ uint32_t smem_u32(const void* p) {
    uint32_t a;
    asm("{ .reg .u64 t; cvta.to.shared.u64 t, %1; cvt.u32.u64 %0, t; }" : "=r"(a) : "l"(p));
    return a;
}

#define LDMX4(r0, r1, r2, r3, a)                                              \
    asm volatile("ldmatrix.sync.aligned.m8n8.x4.shared.b16 {%0,%1,%2,%3},[%4];" \
                 : "=r"(r0), "=r"(r1), "=r"(r2), "=r"(r3) : "r"(a))

// fp16-accumulator HMMA: D,C packed half2 pairs {c0c1, c2c3}
#define MMA16816H(c, a0, a1, a2, a3, b0, b1)                                  \
    asm volatile("mma.sync.aligned.m16n8k16.row.col.f16.f16.f16.f16 "         \
                 "{%0,%1},{%2,%3,%4,%5},{%6,%7},{%0,%1};"                     \
                 : "+r"((c)[0]), "+r"((c)[1])                                 \
                 : "r"(a0), "r"(a1), "r"(a2), "r"(a3), "r"(b0), "r"(b1))

// branchless top-2 on packed (distance|index) keys: 3 IMNMX
#define TOP2(b1, b2, k) do {                       \
    uint32_t _mx = max((b1), (k));                 \
    (b1) = min((b1), (k));                         \
    (b2) = min((b2), _mx); } while (0)

// key = (bits(d') & ~0x7FF) | idx  (d' positive via +256 bias in esqB)
__device__ __forceinline__ uint32_t packkey(float d, int idx) {
    return (__float_as_uint(d) & 0xFFFFF800u) | (uint32_t)idx;
}

// fp16 codebook + exact fp32 esq (R1 accumulation order); also resets accumulators.
__global__ void k_prep(const float* __restrict__ e) {
    if (blockIdx.x == 0 && threadIdx.x == 0) { g_loss = 0.0; g_done = 0; }
    int k = blockIdx.x * blockDim.x + threadIdx.x;
    if (k >= KC) return;
    const float4* er = (const float4*)(e + (size_t)k * ZD);
    uint2* br = (uint2*)(g_B + (size_t)k * ZD);
    float s0 = 0.f, s1 = 0.f, s2 = 0.f, s3 = 0.f;
    #pragma unroll
    for (int i = 0; i < 16; i++) {
        float4 v = er[i];
        s0 = fmaf(v.x, v.x, s0);
        s1 = fmaf(v.y, v.y, s1);
        s2 = fmaf(v.z, v.z, s2);
        s3 = fmaf(v.w, v.w, s3);
        __half2 p0 = __floats2half2_rn(v.x, v.y);
        __half2 p1 = __floats2half2_rn(v.z, v.w);
        uint2 o;
        o.x = *reinterpret_cast<uint32_t*>(&p0);
        o.y = *reinterpret_cast<uint32_t*>(&p1);
        br[i] = o;
    }
    g_esq[k] = (s0 + s1) + (s2 + s3);
}

__device__ __forceinline__ void prefetch_B(int t, int buf, uint32_t sb, int tid) {
    const char* src = (const char*)g_B + (size_t)t * NTILE * ZD * 2;
    uint32_t dst0 = sb + SM_B + buf * BTILE_B;
    #pragma unroll
    for (int j = 0; j < 4; j++) {
        int ch = j * TPB + tid;          // 1024 chunks of 16B
        int row = ch >> 3, c = ch & 7;
        asm volatile("cp.async.cg.shared.global [%0], [%1], 16;"
                     :: "r"(dst0 + row * ROWB + c * 16),
                        "l"(src + row * 128 + c * 16) : "memory");
    }
}

__global__ __launch_bounds__(TPB, 2)
void k_main(const float* __restrict__ z, const float* __restrict__ e,
            float* __restrict__ out) {
    extern __shared__ char smem[];
    const uint32_t sb = smem_u32(smem);
    const int tid = threadIdx.x, wid = tid >> 5, lane = tid & 31;
    const int mw = wid & 3, nw = wid >> 2;

    // ---- A: convert 128 z-rows to fp16 (2 threads/row) ----
    {
        const int ar0 = tid >> 1, hf = tid & 1;
        const float4* zp = (const float4*)(z + (size_t)(blockIdx.x * MCTA + ar0) * ZD + hf * 32);
        char* ar = smem + SM_A + ar0 * ROWB + hf * 64;
        #pragma unroll
        for (int i = 0; i < 8; i++) {
            float4 v = zp[i];
            __half2 p0 = __floats2half2_rn(v.x, v.y);
            __half2 p1 = __floats2half2_rn(v.z, v.w);
            *(uint32_t*)(ar + 8 * i)     = *reinterpret_cast<uint32_t*>(&p0);
            *(uint32_t*)(ar + 8 * i + 4) = *reinterpret_cast<uint32_t*>(&p1);
        }
    }
    // esq -> smem: biased copy (epilogue) + exact copy (rescore)
    {
        float4* db = (float4*)(smem + SM_ESQB);
        float4* dx = (float4*)(smem + SM_ESQ);
        const float4* s = (const float4*)g_esq;
        #pragma unroll
        for (int i = 0; i < 2; i++) {
            float4 v = s[i * TPB + tid];
            dx[i * TPB + tid] = v;
            v.x += DBIAS; v.y += DBIAS; v.z += DBIAS; v.w += DBIAS;
            db[i * TPB + tid] = v;
        }
    }
    prefetch_B(0, 0, sb, tid);
    asm volatile("cp.async.commit_group;" ::: "memory");

    const float* esqb_s = (const float*)(smem + SM_ESQB);
    const float* esq_s  = (const float*)(smem + SM_ESQ);

    // ldmatrix lane addresses (fragment mappings verified R8-R15)
    const uint32_t a_l = sb + SM_A
        + (uint32_t)(mw * 32 + (lane & 7) + ((lane >> 3) & 1) * 8) * ROWB
        + (lane >> 4) * 16;
    const uint32_t b_l = sb + SM_B
        + (uint32_t)(nw * 64 + (lane & 7) + (lane >> 4) * 8) * ROWB
        + ((lane >> 3) & 1) * 16;

    // A is loop-invariant: hoist ALL A fragments into registers (one-time LDSM)
    __syncthreads();                 // A conversion visible CTA-wide
    uint32_t af[2][4][4];
    #pragma unroll
    for (int f = 0; f < 2; f++)
        #pragma unroll
        for (int ks = 0; ks < 4; ks++)
            LDMX4(af[f][ks][0], af[f][ks][1], af[f][ks][2], af[f][ks][3],
                  a_l + f * 16 * ROWB + ks * 32);

    uint32_t kb1[4], kb2[4];
    #pragma unroll
    for (int s = 0; s < 4; s++) { kb1[s] = 0xFFFFFFFFu; kb2[s] = 0xFFFFFFFFu; }

    for (int t = 0; t < NT; t++) {
        asm volatile("cp.async.wait_group 0;" ::: "memory");
        __syncthreads();
        if (t + 1 < NT) {
            prefetch_B(t + 1, (t + 1) & 1, sb, tid);
            asm volatile("cp.async.commit_group;" ::: "memory");
        }
        const uint32_t bb = b_l + (t & 1) * BTILE_B;
        const int colb0 = t * NTILE + nw * 64 + (lane & 3) * 2;

        uint32_t acc[2][8][2];
        #pragma unroll
        for (int f = 0; f < 2; f++)
            #pragma unroll
            for (int g = 0; g < 8; g++) { acc[f][g][0] = 0u; acc[f][g][1] = 0u; }

        #pragma unroll
        for (int ks = 0; ks < 4; ks++) {
            uint32_t bx[8], by[8];
            #pragma unroll
            for (int q = 0; q < 4; q++)
                LDMX4(bx[2 * q], by[2 * q], bx[2 * q + 1], by[2 * q + 1],
                      bb + q * 16 * ROWB + ks * 32);
            #pragma unroll
            for (int f = 0; f < 2; f++)
                #pragma unroll
                for (int g = 0; g < 8; g++)
                    MMA16816H(acc[f][g], af[f][ks][0], af[f][ks][1],
                              af[f][ks][2], af[f][ks][3], bx[g], by[g]);
        }

        #pragma unroll
        for (int g = 0; g < 8; g++) {
            const int col = colb0 + g * 8;
            const float2 ee = *(const float2*)(esqb_s + col);
            #pragma unroll
            for (int f = 0; f < 2; f++) {
                const int s0 = 2 * f, s1 = 2 * f + 1;
                float2 v01 = __half22float2(*reinterpret_cast<__half2*>(&acc[f][g][0]));
                float2 v23 = __half22float2(*reinterpret_cast<__half2*>(&acc[f][g][1]));
                float d00 = fmaf(-2.f, v01.x, ee.x);
                float d01 = fmaf(-2.f, v01.y, ee.y);
                float d10 = fmaf(-2.f, v23.x, ee.x);
                float d11 = fmaf(-2.f, v23.y, ee.y);
                TOP2(kb1[s0], kb2[s0], packkey(d00, col));
                TOP2(kb1[s0], kb2[s0], packkey(d01, col + 1));
                TOP2(kb1[s1], kb2[s1], packkey(d10, col));
                TOP2(kb1[s1], kb2[s1], packkey(d11, col + 1));
            }
        }
    }

    // ---- publish candidate keys (overlay B region) ----
    __syncthreads();
    uint32_t* keys = (uint32_t*)(smem + SM_CAND);
    #pragma unroll
    for (int s = 0; s < 4; s++) {
        int rl = mw * 32 + (s >> 1) * 16 + (lane >> 2) + (s & 1) * 8;
        int p  = (nw * 4 + (lane & 3)) * 2;
        keys[rl * CANDS + p]     = kb1[s];
        keys[rl * CANDS + p + 1] = kb2[s];
    }
    __syncthreads();

    // ---- rescue: 2 threads/row, each rescores 2 of the 4 coarsely-best ----
    const int r  = tid & 127, hf2 = tid >> 7;
    const int row = blockIdx.x * MCTA + r;
    float zr[ZD];
    {
        const float4* zp = (const float4*)(z + (size_t)row * ZD);
        #pragma unroll
        for (int i = 0; i < ZD / 4; i++) {
            float4 v = zp[i];
            zr[4*i] = v.x; zr[4*i+1] = v.y; zr[4*i+2] = v.z; zr[4*i+3] = v.w;
        }
    }
    uint32_t used = 0;
    float bd = CUDART_INF_F;
    int   bi = KC;
    #pragma unroll
    for (int j = 0; j < 4; j++) {
        uint32_t mn = 0xFFFFFFFFu; int mp = 0;
        #pragma unroll
        for (int p = 0; p < 16; p++) {
            uint32_t k = keys[r * CANDS + p];
            k = ((used >> p) & 1u) ? 0xFFFFFFFFu : k;
            if (k < mn) { mn = k; mp = p; }
        }
        used |= 1u << mp;
        if ((j >> 1) == hf2) {                 // this thread rescores ranks {2hf2, 2hf2+1}
            int idx = (int)(mn & 0x7FFu);
            const float4* ep = (const float4*)(e + (size_t)idx * ZD);
            float a0=0.f,a1=0.f,a2=0.f,a3=0.f;
            #pragma unroll
            for (int i = 0; i < ZD / 4; i++) {
                float4 v = ep[i];
                a0 = fmaf(zr[4*i],   v.x, a0); a1 = fmaf(zr[4*i+1], v.y, a1);
                a2 = fmaf(zr[4*i+2], v.z, a2); a3 = fmaf(zr[4*i+3], v.w, a3);
            }
            float d = esq_s[idx] - 2.0f * ((a0 + a1) + (a2 + a3));
            if (d < bd || (d == bd && idx < bi)) { bd = d; bi = idx; }
        }
    }
    {
        float* resd = (float*)(smem + SM_RES);
        int*   resi = (int*)(smem + SM_RES + 2 * MCTA * 4);
        resd[hf2 * MCTA + r] = bd;
        resi[hf2 * MCTA + r] = bi;
    }
    __syncthreads();

    // ---- combine halves + outputs (threads 0..127) ----
    if (tid < MCTA) {
        const float* resd = (const float*)(smem + SM_RES);
        const int*   resi = (const int*)(smem + SM_RES + 2 * MCTA * 4);
        float d0 = resd[r], d1 = resd[MCTA + r];
        int   i0 = resi[r], i1 = resi[MCTA + r];
        int win = (d1 < d0 || (d1 == d0 && i1 < i0)) ? i1 : i0;

        float lsum = 0.f;
        const float4* ep = (const float4*)(e + (size_t)win * ZD);
        float4* orow = (float4*)(out + (size_t)row * ZD);
        #pragma unroll
        for (int i = 0; i < ZD / 4; i++) {
            float4 v = ep[i];
            float dx = zr[4*i]   - v.x, dy = zr[4*i+1] - v.y;
            float dz = zr[4*i+2] - v.z, dw = zr[4*i+3] - v.w;
            lsum += dx*dx + dy*dy + dz*dz + dw*dw;
            orow[i] = v;
        }
        out[(size_t)NR * ZD + row] = (float)win;

        #pragma unroll
        for (int s = 16; s > 0; s >>= 1)
            lsum += __shfl_xor_sync(0xFFFFFFFFu, lsum, s);
        if (lane == 0) atomicAdd(&g_loss, (double)lsum);
    }

    // ---- last CTA finalizes the loss ----
    __syncthreads();
    if (tid == 0) {
        __threadfence();
        int done = atomicAdd(&g_done, 1);
        if (done == GRID - 1)
            out[(size_t)NR * ZD + NR] = (float)(g_loss / ((double)NR * (double)ZD));
    }
}

extern "C" void kernel_launch(void* const* d_in, const int* in_sizes, int n_in,
                              void* d_out, int out_size) {
    const float* z = (const float*)d_in[0];
    const float* e = (const float*)d_in[1];
    float* out = (float*)d_out;

    cudaFuncSetAttribute(k_main, cudaFuncAttributeMaxDynamicSharedMemorySize, SMEM_TOTAL);
    k_prep<<<(KC + 127) / 128, 128>>>(e);
    k_main<<<GRID, TPB, SMEM_TOTAL>>>(z, e, out);
}